// round 1
// baseline (speedup 1.0000x reference)
#include <cuda_runtime.h>
#include <math.h>

#define N_NODES 4096
#define N_EDGES 32768
#define DIM 64
#define EHID 128
#define NUM_STEPS 3

// ---------------- scratch (device globals; no allocation allowed) ----------
__device__ float g_h[N_NODES * DIM];      // h == GRU hidden (always identical)
__device__ float g_e[N_EDGES * EHID];     // edge features
__device__ float g_agg[N_NODES * DIM];    // scatter-add accumulator
__device__ float g_m[N_NODES * DIM];      // conv output m

// ---------------- K1: h = relu(node_feats @ W_p + b_p) ---------------------
__global__ void k_proj_nodes(const float* __restrict__ nf,
                             const float* __restrict__ Wp,
                             const float* __restrict__ bp) {
    __shared__ float s[4 * 64];
    int tid = threadIdx.x;
    int n0 = blockIdx.x * 4;
    s[tid] = nf[(size_t)n0 * 64 + tid];
    __syncthreads();
    int nl = tid >> 6, c = tid & 63;
    float sum = bp[c];
#pragma unroll 16
    for (int k = 0; k < 64; k++) sum += s[nl * 64 + k] * Wp[k * 64 + c];
    g_h[(size_t)(n0 + nl) * 64 + c] = fmaxf(sum, 0.f);
}

// ---------------- K2: e = relu(edge_attr @ W_pe + b_pe) --------------------
__global__ void k_proj_edges(const float* __restrict__ ea,
                             const float* __restrict__ Wpe,
                             const float* __restrict__ bpe) {
    __shared__ float s[2 * 16];
    int tid = threadIdx.x;
    int e0 = blockIdx.x * 2;
    if (tid < 32) s[tid] = ea[(size_t)e0 * 16 + tid];
    __syncthreads();
    int el = tid >> 7, c = tid & 127;
    float sum = bpe[c];
#pragma unroll
    for (int k = 0; k < 16; k++) sum += s[el * 16 + k] * Wpe[k * 128 + c];
    g_e[(size_t)(e0 + el) * 128 + c] = fmaxf(sum, 0.f);
}

// ---------------- zero agg -------------------------------------------------
__global__ void k_zero() {
    int idx = blockIdx.x * blockDim.x + threadIdx.x;
    for (int i = idx; i < N_NODES * DIM; i += gridDim.x * blockDim.x)
        g_agg[i] = 0.f;
}

// ---------------- K4: fused NNConv message + scatter -----------------------
// Per 64-edge block: msg[l,f] = sum_d h[src[l],d] * relu(b_nn[d*64+f] +
//                                  sum_k e[l,k] * W_nn[k, d*64+f])
// smem (floats): eT 128x68 @0 (8704) | hsT 64 rows stride 65 @8704 (4160)
//                | wt 128x64 @12864 (8192)  => 21056 floats = 84224 B
#define K4_SMEM_FLOATS 21056
extern "C" __global__ void __launch_bounds__(256, 2)
k_nnconv(const int* __restrict__ eidx,
         const float* __restrict__ W_nn,
         const float* __restrict__ b_nn) {
    extern __shared__ float sm[];
    float* eT  = sm;           // [k*68 + l]
    float* hsT = sm + 8704;    // [d*65 + l]
    float* wt  = sm + 12864;   // [k*64 + f]
    __shared__ int sc[64], tc[64];

    const int tid = threadIdx.x;
    const int e0 = blockIdx.x * 64;

    if (tid < 64) {
        sc[tid] = eidx[e0 + tid];             // source
        tc[tid] = eidx[N_EDGES + e0 + tid];   // target
    }
    __syncthreads();

    // e tile, transposed
#pragma unroll
    for (int r = 0; r < 32; r++) {
        int idx = r * 256 + tid;
        int l = idx >> 7, k = idx & 127;
        eT[k * 68 + l] = g_e[(size_t)(e0 + l) * 128 + k];
    }
    // gathered h[src], transposed
#pragma unroll
    for (int r = 0; r < 16; r++) {
        int idx = r * 256 + tid;
        int l = idx >> 6, d = idx & 63;
        hsT[d * 65 + l] = g_h[(size_t)sc[l] * 64 + d];
    }

    const int ty = tid >> 4, tx = tid & 15;   // 16x16 threads, 4x4 tile each
    float msg[4][4] = {};

    for (int d = 0; d < 64; d++) {
        __syncthreads();  // protect wt (also covers initial tile loads)
        // load W_nn[:, d*64 : d*64+64]  (128x64) as float4
#pragma unroll
        for (int r = 0; r < 8; r++) {
            int idx = r * 256 + tid;          // float4 index, 0..2047
            int k = idx >> 4, fq = idx & 15;
            ((float4*)wt)[k * 16 + fq] =
                ((const float4*)W_nn)[(size_t)k * 1024 + d * 16 + fq];
        }
        __syncthreads();

        float zz[4][4] = {};
#pragma unroll 8
        for (int k = 0; k < 128; k++) {
            float4 a4 = *(const float4*)&eT[k * 68 + ty * 4];
            float4 b4 = *(const float4*)&wt[k * 64 + tx * 4];
            float av[4] = {a4.x, a4.y, a4.z, a4.w};
            float bv[4] = {b4.x, b4.y, b4.z, b4.w};
#pragma unroll
            for (int i = 0; i < 4; i++)
#pragma unroll
                for (int j = 0; j < 4; j++) zz[i][j] += av[i] * bv[j];
        }

        float4 bb4 = *(const float4*)&b_nn[d * 64 + tx * 4];
        float bv[4] = {bb4.x, bb4.y, bb4.z, bb4.w};
#pragma unroll
        for (int i = 0; i < 4; i++) {
            float hv = hsT[d * 65 + ty * 4 + i];
#pragma unroll
            for (int j = 0; j < 4; j++) {
                float z = fmaxf(zz[i][j] + bv[j], 0.f);
                msg[i][j] += hv * z;
            }
        }
    }

    // scatter-add to agg[target]
#pragma unroll
    for (int i = 0; i < 4; i++) {
        int t = tc[ty * 4 + i];
        float* dst = &g_agg[(size_t)t * 64 + tx * 4];
#pragma unroll
        for (int j = 0; j < 4; j++) atomicAdd(dst + j, msg[i][j]);
    }
}

// ---------------- K5: m = relu(agg + h @ W_root + b_conv) ------------------
__global__ void k_conv(const float* __restrict__ Wr,
                       const float* __restrict__ bc) {
    __shared__ float s[4 * 64];
    int tid = threadIdx.x;
    int n0 = blockIdx.x * 4;
    s[tid] = g_h[(size_t)n0 * 64 + tid];
    __syncthreads();
    int nl = tid >> 6, c = tid & 63;
    float sum = bc[c] + g_agg[(size_t)(n0 + nl) * 64 + c];
#pragma unroll 16
    for (int k = 0; k < 64; k++) sum += s[nl * 64 + k] * Wr[k * 64 + c];
    g_m[(size_t)(n0 + nl) * 64 + c] = fmaxf(sum, 0.f);
}

// ---------------- K6: fused GRU cell (one node per block) ------------------
__global__ void k_gru(const float* __restrict__ wih,
                      const float* __restrict__ whh,
                      const float* __restrict__ bih,
                      const float* __restrict__ bhh) {
    __shared__ float mr[64], hr[64], gi[192], gh[192];
    int n = blockIdx.x;
    int c = threadIdx.x;   // 0..191
    if (c < 64) {
        mr[c] = g_m[(size_t)n * 64 + c];
        hr[c] = g_h[(size_t)n * 64 + c];
    }
    __syncthreads();
    float si = bih[c], sh = bhh[c];
#pragma unroll 16
    for (int k = 0; k < 64; k++) {
        si += mr[k] * wih[k * 192 + c];
        sh += hr[k] * whh[k * 192 + c];
    }
    gi[c] = si; gh[c] = sh;
    __syncthreads();
    if (c < 64) {
        float r = 1.f / (1.f + expf(-(gi[c] + gh[c])));
        float z = 1.f / (1.f + expf(-(gi[64 + c] + gh[64 + c])));
        float nc = tanhf(gi[128 + c] + r * gh[128 + c]);
        g_h[(size_t)n * 64 + c] = (1.f - z) * nc + z * hr[c];
    }
}

// ---------------- K7: fused edge-update MLP --------------------------------
// per edge: e_new = relu(relu([h_src,h_tgt,e] @ W1 + b1) @ W2 + b2)
// smem: eiT 256x68 @0 (17408) | wt 64x128 @17408 (8192) | tT 128x68 @25600 (8704)
//  => 34304 floats = 137216 B
#define K7_SMEM_FLOATS 34304
extern "C" __global__ void __launch_bounds__(256, 1)
k_edgeup(const int* __restrict__ eidx,
         const float* __restrict__ W1, const float* __restrict__ b1,
         const float* __restrict__ W2, const float* __restrict__ b2) {
    extern __shared__ float sm[];
    float* eiT = sm;            // [k*68 + l], k < 256
    float* wt  = sm + 17408;    // [kk*128 + f]
    float* tT  = sm + 25600;    // [f*68 + l]
    __shared__ int sc[64], tc[64];

    int tid = threadIdx.x;
    int e0 = blockIdx.x * 64;
    if (tid < 64) {
        sc[tid] = eidx[e0 + tid];
        tc[tid] = eidx[N_EDGES + e0 + tid];
    }
    __syncthreads();
#pragma unroll
    for (int r = 0; r < 16; r++) {
        int idx = r * 256 + tid; int l = idx >> 6, k = idx & 63;
        eiT[k * 68 + l] = g_h[(size_t)sc[l] * 64 + k];
    }
#pragma unroll
    for (int r = 0; r < 16; r++) {
        int idx = r * 256 + tid; int l = idx >> 6, k = idx & 63;
        eiT[(64 + k) * 68 + l] = g_h[(size_t)tc[l] * 64 + k];
    }
#pragma unroll
    for (int r = 0; r < 32; r++) {
        int idx = r * 256 + tid; int l = idx >> 7, k = idx & 127;
        eiT[(128 + k) * 68 + l] = g_e[(size_t)(e0 + l) * 128 + k];
    }

    const int ty = tid >> 4, tx = tid & 15;  // l = ty*4+i, f = tx*8+j
    float acc[4][8] = {};

    for (int kc = 0; kc < 4; kc++) {
        __syncthreads();
#pragma unroll
        for (int r = 0; r < 8; r++) {
            int idx = r * 256 + tid;          // float4 index 0..2047
            int kk = idx >> 5, fq = idx & 31;
            ((float4*)wt)[kk * 32 + fq] =
                ((const float4*)W1)[(size_t)(kc * 64 + kk) * 32 + fq];
        }
        __syncthreads();
#pragma unroll 8
        for (int kk = 0; kk < 64; kk++) {
            int k = kc * 64 + kk;
            float4 a4 = *(const float4*)&eiT[k * 68 + ty * 4];
            float4 c0 = *(const float4*)&wt[kk * 128 + tx * 8];
            float4 c1 = *(const float4*)&wt[kk * 128 + tx * 8 + 4];
            float av[4] = {a4.x, a4.y, a4.z, a4.w};
            float bv[8] = {c0.x, c0.y, c0.z, c0.w, c1.x, c1.y, c1.z, c1.w};
#pragma unroll
            for (int i = 0; i < 4; i++)
#pragma unroll
                for (int j = 0; j < 8; j++) acc[i][j] += av[i] * bv[j];
        }
    }

    // layer-1 activation -> tT (transposed)
#pragma unroll
    for (int j = 0; j < 8; j++) {
        float bb = b1[tx * 8 + j];
#pragma unroll
        for (int i = 0; i < 4; i++)
            tT[(tx * 8 + j) * 68 + ty * 4 + i] = fmaxf(acc[i][j] + bb, 0.f);
    }

    float acc2[4][8] = {};
    for (int kc = 0; kc < 2; kc++) {
        __syncthreads();
#pragma unroll
        for (int r = 0; r < 8; r++) {
            int idx = r * 256 + tid;
            int kk = idx >> 5, fq = idx & 31;
            ((float4*)wt)[kk * 32 + fq] =
                ((const float4*)W2)[(size_t)(kc * 64 + kk) * 32 + fq];
        }
        __syncthreads();
#pragma unroll 8
        for (int kk = 0; kk < 64; kk++) {
            int k = kc * 64 + kk;
            float4 a4 = *(const float4*)&tT[k * 68 + ty * 4];
            float4 c0 = *(const float4*)&wt[kk * 128 + tx * 8];
            float4 c1 = *(const float4*)&wt[kk * 128 + tx * 8 + 4];
            float av[4] = {a4.x, a4.y, a4.z, a4.w};
            float bv[8] = {c0.x, c0.y, c0.z, c0.w, c1.x, c1.y, c1.z, c1.w};
#pragma unroll
            for (int i = 0; i < 4; i++)
#pragma unroll
                for (int j = 0; j < 8; j++) acc2[i][j] += av[i] * bv[j];
        }
    }

#pragma unroll
    for (int i = 0; i < 4; i++) {
        size_t base = (size_t)(e0 + ty * 4 + i) * 128 + tx * 8;
#pragma unroll
        for (int j = 0; j < 8; j++)
            g_e[base + j] = fmaxf(acc2[i][j] + b2[tx * 8 + j], 0.f);
    }
}

// ---------------- output copy: [h (4096x64), e (32768x128)] ----------------
__global__ void k_out(float4* __restrict__ out) {
    const int H4 = (N_NODES * DIM) / 4;           // 65536
    const int T4 = H4 + (N_EDGES * EHID) / 4;     // 1114112
    int idx = blockIdx.x * blockDim.x + threadIdx.x;
    const float4* h4 = (const float4*)g_h;
    const float4* e4 = (const float4*)g_e;
    for (int i = idx; i < T4; i += gridDim.x * blockDim.x)
        out[i] = (i < H4) ? h4[i] : e4[i - H4];
}

// ---------------- launcher -------------------------------------------------
extern "C" void kernel_launch(void* const* d_in, const int* in_sizes, int n_in,
                              void* d_out, int out_size) {
    const float* nf   = (const float*)d_in[0];
    const float* ea   = (const float*)d_in[1];
    const int*   eidx = (const int*)  d_in[2];
    const float* Wp   = (const float*)d_in[3];
    const float* bp   = (const float*)d_in[4];
    const float* Wpe  = (const float*)d_in[5];
    const float* bpe  = (const float*)d_in[6];
    const float* Wnn  = (const float*)d_in[7];
    const float* bnn  = (const float*)d_in[8];
    const float* Wr   = (const float*)d_in[9];
    const float* bc   = (const float*)d_in[10];
    const float* wih  = (const float*)d_in[11];
    const float* whh  = (const float*)d_in[12];
    const float* bih  = (const float*)d_in[13];
    const float* bhh  = (const float*)d_in[14];
    const float* We1  = (const float*)d_in[15];
    const float* be1  = (const float*)d_in[16];
    const float* We2  = (const float*)d_in[17];
    const float* be2  = (const float*)d_in[18];

    cudaFuncSetAttribute(k_nnconv, cudaFuncAttributeMaxDynamicSharedMemorySize,
                         K4_SMEM_FLOATS * 4);
    cudaFuncSetAttribute(k_edgeup, cudaFuncAttributeMaxDynamicSharedMemorySize,
                         K7_SMEM_FLOATS * 4);

    k_proj_nodes<<<N_NODES / 4, 256>>>(nf, Wp, bp);
    k_proj_edges<<<N_EDGES / 2, 256>>>(ea, Wpe, bpe);

    for (int step = 0; step < NUM_STEPS; step++) {
        k_zero<<<256, 256>>>();
        k_nnconv<<<N_EDGES / 64, 256, K4_SMEM_FLOATS * 4>>>(eidx, Wnn, bnn);
        k_conv<<<N_NODES / 4, 256>>>(Wr, bc);
        k_gru<<<N_NODES, 192>>>(wih, whh, bih, bhh);
        k_edgeup<<<N_EDGES / 64, 256, K7_SMEM_FLOATS * 4>>>(eidx, We1, be1, We2, be2);
    }

    k_out<<<2048, 256>>>((float4*)d_out);
}

// round 3
// speedup vs baseline: 2.0333x; 2.0333x over previous
#include <cuda_runtime.h>
#include <cuda_bf16.h>
#include <math.h>
#include <stdint.h>

#define N_NODES 4096
#define N_EDGES 32768
#define DIM 64
#define EHID 128
#define NUM_STEPS 3

// ---------------- scratch (device globals) ---------------------------------
__device__ float g_h[N_NODES * DIM];
__device__ float g_e[N_EDGES * EHID];
__device__ float g_agg[N_NODES * DIM];
__device__ float g_m[N_NODES * DIM];
__device__ __nv_bfloat16 g_ehi[N_EDGES * EHID];
__device__ __nv_bfloat16 g_elo[N_EDGES * EHID];
__device__ __nv_bfloat16 g_Wthi[4096 * 128];   // [n][k] = W_nn[k][n] hi part
__device__ __nv_bfloat16 g_Wtlo[4096 * 128];   // lo part

// ---------------- helpers ---------------------------------------------------
__device__ __forceinline__ uint32_t smem_u32(const void* p) {
    uint32_t a;
    asm("{ .reg .u64 t; cvta.to.shared.u64 t, %1; cvt.u32.u64 %0, t; }"
        : "=r"(a) : "l"(p));
    return a;
}
#define LDSM4(r, addr) \
    asm volatile("ldmatrix.sync.aligned.m8n8.x4.shared.b16 {%0,%1,%2,%3}, [%4];" \
        : "=r"((r)[0]), "=r"((r)[1]), "=r"((r)[2]), "=r"((r)[3]) : "r"(addr))
#define MMA16816(C, A, b0, b1) \
    asm volatile("mma.sync.aligned.m16n8k16.row.col.f32.bf16.bf16.f32 " \
        "{%0,%1,%2,%3},{%4,%5,%6,%7},{%8,%9},{%0,%1,%2,%3};" \
        : "+f"((C)[0]), "+f"((C)[1]), "+f"((C)[2]), "+f"((C)[3]) \
        : "r"((A)[0]), "r"((A)[1]), "r"((A)[2]), "r"((A)[3]), "r"(b0), "r"(b1))
#define CP_ASYNC16(dst, src) \
    asm volatile("cp.async.ca.shared.global [%0], [%1], 16;" :: "r"(dst), "l"(src))
#define CP_COMMIT() asm volatile("cp.async.commit_group;")
#define CP_WAIT_ALL() asm volatile("cp.async.wait_all;")

// ---------------- K1: h = relu(node_feats @ W_p + b_p) ---------------------
__global__ void k_proj_nodes(const float* __restrict__ nf,
                             const float* __restrict__ Wp,
                             const float* __restrict__ bp) {
    __shared__ float s[4 * 64];
    int tid = threadIdx.x;
    int n0 = blockIdx.x * 4;
    s[tid] = nf[(size_t)n0 * 64 + tid];
    __syncthreads();
    int nl = tid >> 6, c = tid & 63;
    float sum = bp[c];
#pragma unroll 16
    for (int k = 0; k < 64; k++) sum += s[nl * 64 + k] * Wp[k * 64 + c];
    g_h[(size_t)(n0 + nl) * 64 + c] = fmaxf(sum, 0.f);
}

// ---------------- K2: e = relu(edge_attr @ W_pe + b_pe) + bf16 split -------
__global__ void k_proj_edges(const float* __restrict__ ea,
                             const float* __restrict__ Wpe,
                             const float* __restrict__ bpe) {
    __shared__ float s[2 * 16];
    int tid = threadIdx.x;
    int e0 = blockIdx.x * 2;
    if (tid < 32) s[tid] = ea[(size_t)e0 * 16 + tid];
    __syncthreads();
    int el = tid >> 7, c = tid & 127;
    float sum = bpe[c];
#pragma unroll
    for (int k = 0; k < 16; k++) sum += s[el * 16 + k] * Wpe[k * 128 + c];
    float v = fmaxf(sum, 0.f);
    size_t idx = (size_t)(e0 + el) * 128 + c;
    g_e[idx] = v;
    __nv_bfloat16 hi = __float2bfloat16(v);
    g_ehi[idx] = hi;
    g_elo[idx] = __float2bfloat16(v - __bfloat162float(hi));
}

// ---------------- W_nn transpose + bf16 split ------------------------------
__global__ void k_wsplit(const float* __restrict__ W) {
    __shared__ float t[32][33];
    int x = threadIdx.x, y = threadIdx.y;           // 32 x 8
    int nb = blockIdx.x * 32, kb = blockIdx.y * 32;
#pragma unroll
    for (int i = 0; i < 4; i++)
        t[y + 8 * i][x] = W[(size_t)(kb + y + 8 * i) * 4096 + nb + x];
    __syncthreads();
#pragma unroll
    for (int i = 0; i < 4; i++) {
        float v = t[x][y + 8 * i];
        size_t o = (size_t)(nb + y + 8 * i) * 128 + kb + x;
        __nv_bfloat16 hi = __float2bfloat16(v);
        g_Wthi[o] = hi;
        g_Wtlo[o] = __float2bfloat16(v - __bfloat162float(hi));
    }
}

// ---------------- zero agg -------------------------------------------------
__global__ void k_zero() {
    int idx = blockIdx.x * blockDim.x + threadIdx.x;
    for (int i = idx; i < N_NODES * DIM; i += gridDim.x * blockDim.x)
        g_agg[i] = 0.f;
}

// ---------------- K4: NNConv via warp mma.sync (bf16 3-split) --------------
// CTA = 128 edges, 8 warps (16 edges each). A (e-tile, hi/lo) lives in
// registers for all 64 d-chunks. Per d: W^T tile [64n x 128k] hi/lo is
// cp.async double-buffered, B frags via ldmatrix, 3-split MMA into C frags
// pre-seeded with bias, then relu * h_src accumulated into msg frags.
// smem: sc@0(512) tc@512(512) bias@1024(16384) hs@17408(33280)
//       AB@51200 (2 x 34816 = 69632; A staging hi/lo aliases B double-buffer)
#define NC_SMEM 120832
#define OFF_BIAS 1024
#define OFF_HS   17408
#define OFF_AB   51200
extern "C" __global__ void __launch_bounds__(256, 1)
k_nnconv_mma(const int* __restrict__ eidx, const float* __restrict__ b_nn) {
    extern __shared__ char sm[];
    int* sc = (int*)sm;
    int* tcs = (int*)(sm + 512);
    float* sbias = (float*)(sm + OFF_BIAS);
    float* hs = (float*)(sm + OFF_HS);
    char* AB = sm + OFF_AB;
    const uint32_t ABu = smem_u32(AB);

    const int tid = threadIdx.x;
    const int e0 = blockIdx.x * 128;
    const int w = tid >> 5, lane = tid & 31;

    if (tid < 128) sc[tid] = eidx[e0 + tid];
    else           tcs[tid - 128] = eidx[N_EDGES + e0 + (tid - 128)];
#pragma unroll
    for (int i = 0; i < 4; i++)
        ((float4*)sbias)[i * 256 + tid] = ((const float4*)b_nn)[i * 256 + tid];
    __syncthreads();

    // gathered h[src] -> hs (stride 65 floats), 2 threads per edge
    {
        int l = tid >> 1, d0 = (tid & 1) * 32;
        const float* hrow = g_h + (size_t)sc[l] * 64 + d0;
        float* dst = hs + l * 65 + d0;
#pragma unroll
        for (int i = 0; i < 32; i += 4) {
            float4 v = *(const float4*)(hrow + i);
            dst[i] = v.x; dst[i + 1] = v.y; dst[i + 2] = v.z; dst[i + 3] = v.w;
        }
    }
    // A staging: e hi at AB+0, e lo at AB+34816, row stride 272B
    {
        const uint4* shi = (const uint4*)(g_ehi + (size_t)e0 * 128);
        const uint4* slo = (const uint4*)(g_elo + (size_t)e0 * 128);
#pragma unroll
        for (int it = 0; it < 8; it++) {
            int idx = it * 256 + tid;
            int row = idx >> 4, sl = idx & 15;
            *(uint4*)(AB + row * 272 + sl * 16) = shi[row * 16 + sl];
            *(uint4*)(AB + 34816 + row * 272 + sl * 16) = slo[row * 16 + sl];
        }
    }
    __syncthreads();

    // A fragments (persistent in regs): ahi/alo[kf][4]
    uint32_t ahi[8][4], alo[8][4];
    {
        uint32_t rowA = (uint32_t)(16 * w + ((lane >> 3) & 1) * 8 + (lane & 7));
        uint32_t base = ABu + rowA * 272 + ((lane >> 4) * 16);
#pragma unroll
        for (int kf = 0; kf < 8; kf++) {
            LDSM4(ahi[kf], base + kf * 32);
            LDSM4(alo[kf], base + 34816 + kf * 32);
        }
    }
    __syncthreads();   // A smem consumed; AB becomes the B double-buffer

    // B(0) -> buf 0
    {
        for (int i = tid; i < 2176; i += 256) {
            int row = i / 17, sl = i - row * 17;
            if (sl < 16) {
                int plane = row >> 6, n = row & 63;
                const __nv_bfloat16* gsrc =
                    (plane ? g_Wtlo : g_Wthi) + (size_t)n * 128 + sl * 8;
                CP_ASYNC16(ABu + plane * 17408 + n * 272 + sl * 16, gsrc);
            }
        }
        CP_COMMIT();
    }

    const int gid = lane >> 2, tpair = (lane & 3) * 2;
    const int row0 = 16 * w + gid;
    const float* hvp0 = hs + row0 * 65;
    const float* hvp1 = hs + (row0 + 8) * 65;
    const uint32_t boff = (uint32_t)((lane >> 4) * 17408 + (lane & 7) * 272 +
                                     ((lane >> 3) & 1) * 16);
    float msg[8][4] = {};

    for (int d = 0; d < 64; d++) {
        CP_WAIT_ALL();
        __syncthreads();
        if (d + 1 < 64) {
            char* dstb = AB + ((d + 1) & 1) * 34816;
            uint32_t dstu = ABu + ((d + 1) & 1) * 34816;
            (void)dstb;
            for (int i = tid; i < 2176; i += 256) {
                int row = i / 17, sl = i - row * 17;
                if (sl < 16) {
                    int plane = row >> 6, n = row & 63;
                    const __nv_bfloat16* gsrc = (plane ? g_Wtlo : g_Wthi) +
                        ((size_t)(d + 1) * 64 + n) * 128 + sl * 8;
                    CP_ASYNC16(dstu + plane * 17408 + n * 272 + sl * 16, gsrc);
                }
            }
            CP_COMMIT();
        }

        // seed C with bias
        float C[8][4];
        const float* bptr = sbias + d * 64 + tpair;
#pragma unroll
        for (int nf = 0; nf < 8; nf++) {
            float2 bv = *(const float2*)(bptr + nf * 8);
            C[nf][0] = bv.x; C[nf][1] = bv.y;
            C[nf][2] = bv.x; C[nf][3] = bv.y;
        }
        const uint32_t bb = ABu + (d & 1) * 34816 + boff;
#pragma unroll
        for (int kf = 0; kf < 8; kf++) {
#pragma unroll
            for (int nf = 0; nf < 8; nf++) {
                uint32_t b[4];
                LDSM4(b, bb + nf * 2176 + kf * 32);
                MMA16816(C[nf], ahi[kf], b[0], b[1]);
                MMA16816(C[nf], alo[kf], b[0], b[1]);
                MMA16816(C[nf], ahi[kf], b[2], b[3]);
            }
        }
        float hv0 = hvp0[d], hv1 = hvp1[d];
#pragma unroll
        for (int nf = 0; nf < 8; nf++) {
            msg[nf][0] = fmaf(hv0, fmaxf(C[nf][0], 0.f), msg[nf][0]);
            msg[nf][1] = fmaf(hv0, fmaxf(C[nf][1], 0.f), msg[nf][1]);
            msg[nf][2] = fmaf(hv1, fmaxf(C[nf][2], 0.f), msg[nf][2]);
            msg[nf][3] = fmaf(hv1, fmaxf(C[nf][3], 0.f), msg[nf][3]);
        }
    }

    // scatter-add to agg[target]
    float* d0 = g_agg + (size_t)tcs[row0] * 64 + tpair;
    float* d1 = g_agg + (size_t)tcs[row0 + 8] * 64 + tpair;
#pragma unroll
    for (int nf = 0; nf < 8; nf++) {
        atomicAdd(d0 + nf * 8,     msg[nf][0]);
        atomicAdd(d0 + nf * 8 + 1, msg[nf][1]);
        atomicAdd(d1 + nf * 8,     msg[nf][2]);
        atomicAdd(d1 + nf * 8 + 1, msg[nf][3]);
    }
}

// ---------------- K5: m = relu(agg + h @ W_root + b_conv) ------------------
__global__ void k_conv(const float* __restrict__ Wr,
                       const float* __restrict__ bc) {
    __shared__ float s[4 * 64];
    int tid = threadIdx.x;
    int n0 = blockIdx.x * 4;
    s[tid] = g_h[(size_t)n0 * 64 + tid];
    __syncthreads();
    int nl = tid >> 6, c = tid & 63;
    float sum = bc[c] + g_agg[(size_t)(n0 + nl) * 64 + c];
#pragma unroll 16
    for (int k = 0; k < 64; k++) sum += s[nl * 64 + k] * Wr[k * 64 + c];
    g_m[(size_t)(n0 + nl) * 64 + c] = fmaxf(sum, 0.f);
}

// ---------------- K6: fused GRU cell ---------------------------------------
__global__ void k_gru(const float* __restrict__ wih,
                      const float* __restrict__ whh,
                      const float* __restrict__ bih,
                      const float* __restrict__ bhh) {
    __shared__ float mr[64], hr[64], gi[192], gh[192];
    int n = blockIdx.x;
    int c = threadIdx.x;
    if (c < 64) {
        mr[c] = g_m[(size_t)n * 64 + c];
        hr[c] = g_h[(size_t)n * 64 + c];
    }
    __syncthreads();
    float si = bih[c], sh = bhh[c];
#pragma unroll 16
    for (int k = 0; k < 64; k++) {
        si += mr[k] * wih[k * 192 + c];
        sh += hr[k] * whh[k * 192 + c];
    }
    gi[c] = si; gh[c] = sh;
    __syncthreads();
    if (c < 64) {
        float r = 1.f / (1.f + expf(-(gi[c] + gh[c])));
        float z = 1.f / (1.f + expf(-(gi[64 + c] + gh[64 + c])));
        float nc = tanhf(gi[128 + c] + r * gh[128 + c]);
        g_h[(size_t)n * 64 + c] = (1.f - z) * nc + z * hr[c];
    }
}

// ---------------- K7: fused edge-update MLP (+ bf16 split out) -------------
#define K7_SMEM_FLOATS 34304
extern "C" __global__ void __launch_bounds__(256, 1)
k_edgeup(const int* __restrict__ eidx,
         const float* __restrict__ W1, const float* __restrict__ b1,
         const float* __restrict__ W2, const float* __restrict__ b2) {
    extern __shared__ float smf[];
    float* eiT = smf;
    float* wt  = smf + 17408;
    float* tT  = smf + 25600;
    __shared__ int sc[64], tc[64];

    int tid = threadIdx.x;
    int e0 = blockIdx.x * 64;
    if (tid < 64) {
        sc[tid] = eidx[e0 + tid];
        tc[tid] = eidx[N_EDGES + e0 + tid];
    }
    __syncthreads();
#pragma unroll
    for (int r = 0; r < 16; r++) {
        int idx = r * 256 + tid; int l = idx >> 6, k = idx & 63;
        eiT[k * 68 + l] = g_h[(size_t)sc[l] * 64 + k];
    }
#pragma unroll
    for (int r = 0; r < 16; r++) {
        int idx = r * 256 + tid; int l = idx >> 6, k = idx & 63;
        eiT[(64 + k) * 68 + l] = g_h[(size_t)tc[l] * 64 + k];
    }
#pragma unroll
    for (int r = 0; r < 32; r++) {
        int idx = r * 256 + tid; int l = idx >> 7, k = idx & 127;
        eiT[(128 + k) * 68 + l] = g_e[(size_t)(e0 + l) * 128 + k];
    }

    const int ty = tid >> 4, tx = tid & 15;
    float acc[4][8] = {};

    for (int kc = 0; kc < 4; kc++) {
        __syncthreads();
#pragma unroll
        for (int r = 0; r < 8; r++) {
            int idx = r * 256 + tid;
            int kk = idx >> 5, fq = idx & 31;
            ((float4*)wt)[kk * 32 + fq] =
                ((const float4*)W1)[(size_t)(kc * 64 + kk) * 32 + fq];
        }
        __syncthreads();
#pragma unroll 8
        for (int kk = 0; kk < 64; kk++) {
            int k = kc * 64 + kk;
            float4 a4 = *(const float4*)&eiT[k * 68 + ty * 4];
            float4 c0 = *(const float4*)&wt[kk * 128 + tx * 8];
            float4 c1 = *(const float4*)&wt[kk * 128 + tx * 8 + 4];
            float av[4] = {a4.x, a4.y, a4.z, a4.w};
            float bv[8] = {c0.x, c0.y, c0.z, c0.w, c1.x, c1.y, c1.z, c1.w};
#pragma unroll
            for (int i = 0; i < 4; i++)
#pragma unroll
                for (int j = 0; j < 8; j++) acc[i][j] += av[i] * bv[j];
        }
    }

#pragma unroll
    for (int j = 0; j < 8; j++) {
        float bb = b1[tx * 8 + j];
#pragma unroll
        for (int i = 0; i < 4; i++)
            tT[(tx * 8 + j) * 68 + ty * 4 + i] = fmaxf(acc[i][j] + bb, 0.f);
    }

    float acc2[4][8] = {};
    for (int kc = 0; kc < 2; kc++) {
        __syncthreads();
#pragma unroll
        for (int r = 0; r < 8; r++) {
            int idx = r * 256 + tid;
            int kk = idx >> 5, fq = idx & 31;
            ((float4*)wt)[kk * 32 + fq] =
                ((const float4*)W2)[(size_t)(kc * 64 + kk) * 32 + fq];
        }
        __syncthreads();
#pragma unroll 8
        for (int kk = 0; kk < 64; kk++) {
            int k = kc * 64 + kk;
            float4 a4 = *(const float4*)&tT[k * 68 + ty * 4];
            float4 c0 = *(const float4*)&wt[kk * 128 + tx * 8];
            float4 c1 = *(const float4*)&wt[kk * 128 + tx * 8 + 4];
            float av[4] = {a4.x, a4.y, a4.z, a4.w};
            float bv[8] = {c0.x, c0.y, c0.z, c0.w, c1.x, c1.y, c1.z, c1.w};
#pragma unroll
            for (int i = 0; i < 4; i++)
#pragma unroll
                for (int j = 0; j < 8; j++) acc2[i][j] += av[i] * bv[j];
        }
    }

#pragma unroll
    for (int i = 0; i < 4; i++) {
        size_t base = (size_t)(e0 + ty * 4 + i) * 128 + tx * 8;
#pragma unroll
        for (int j = 0; j < 8; j++) {
            float v = fmaxf(acc2[i][j] + b2[tx * 8 + j], 0.f);
            g_e[base + j] = v;
            __nv_bfloat16 hi = __float2bfloat16(v);
            g_ehi[base + j] = hi;
            g_elo[base + j] = __float2bfloat16(v - __bfloat162float(hi));
        }
    }
}

// ---------------- output copy ----------------------------------------------
__global__ void k_out(float4* __restrict__ out) {
    const int H4 = (N_NODES * DIM) / 4;
    const int T4 = H4 + (N_EDGES * EHID) / 4;
    int idx = blockIdx.x * blockDim.x + threadIdx.x;
    const float4* h4 = (const float4*)g_h;
    const float4* e4 = (const float4*)g_e;
    for (int i = idx; i < T4; i += gridDim.x * blockDim.x)
        out[i] = (i < H4) ? h4[i] : e4[i - H4];
}

// ---------------- launcher -------------------------------------------------
extern "C" void kernel_launch(void* const* d_in, const int* in_sizes, int n_in,
                              void* d_out, int out_size) {
    const float* nf   = (const float*)d_in[0];
    const float* ea   = (const float*)d_in[1];
    const int*   eidx = (const int*)  d_in[2];
    const float* Wp   = (const float*)d_in[3];
    const float* bp   = (const float*)d_in[4];
    const float* Wpe  = (const float*)d_in[5];
    const float* bpe  = (const float*)d_in[6];
    const float* Wnn  = (const float*)d_in[7];
    const float* bnn  = (const float*)d_in[8];
    const float* Wr   = (const float*)d_in[9];
    const float* bc   = (const float*)d_in[10];
    const float* wih  = (const float*)d_in[11];
    const float* whh  = (const float*)d_in[12];
    const float* bih  = (const float*)d_in[13];
    const float* bhh  = (const float*)d_in[14];
    const float* We1  = (const float*)d_in[15];
    const float* be1  = (const float*)d_in[16];
    const float* We2  = (const float*)d_in[17];
    const float* be2  = (const float*)d_in[18];

    cudaFuncSetAttribute(k_nnconv_mma, cudaFuncAttributeMaxDynamicSharedMemorySize, NC_SMEM);
    cudaFuncSetAttribute(k_edgeup, cudaFuncAttributeMaxDynamicSharedMemorySize,
                         K7_SMEM_FLOATS * 4);

    k_wsplit<<<dim3(128, 4), dim3(32, 8)>>>(Wnn);
    k_proj_nodes<<<N_NODES / 4, 256>>>(nf, Wp, bp);
    k_proj_edges<<<N_EDGES / 2, 256>>>(ea, Wpe, bpe);

    for (int step = 0; step < NUM_STEPS; step++) {
        k_zero<<<256, 256>>>();
        k_nnconv_mma<<<N_EDGES / 128, 256, NC_SMEM>>>(eidx, bnn);
        k_conv<<<N_NODES / 4, 256>>>(Wr, bc);
        k_gru<<<N_NODES, 192>>>(wih, whh, bih, bhh);
        k_edgeup<<<N_EDGES / 64, 256, K7_SMEM_FLOATS * 4>>>(eidx, We1, be1, We2, be2);
    }

    k_out<<<2048, 256>>>((float4*)d_out);
}

// round 4
// speedup vs baseline: 3.1058x; 1.5275x over previous
#include <cuda_runtime.h>
#include <cuda_fp16.h>
#include <math.h>
#include <stdint.h>

#define N_NODES 4096
#define N_EDGES 32768
#define DIM 64
#define EHID 128
#define NUM_STEPS 3

// ---------------- scratch (device globals) ---------------------------------
__device__ float g_h[N_NODES * DIM];
__device__ float g_e[N_EDGES * EHID];
__device__ float g_agg[N_NODES * DIM];
__device__ float g_m[N_NODES * DIM];
__device__ __half g_h1[N_NODES * DIM];    // fp16 limb1 of h
__device__ __half g_h2[N_NODES * DIM];    // fp16 limb2
__device__ __half g_e1[N_EDGES * EHID];   // fp16 limb1 of e
__device__ __half g_e2[N_EDGES * EHID];   // fp16 limb2
__device__ __half g_Wt1[4096 * 128];      // W_nn^T [n][k] limb1
__device__ __half g_Wt2[4096 * 128];      // limb2
__device__ __half g_We1T1[128 * 256];     // W_eu1^T [n][k] limb1
__device__ __half g_We1T2[128 * 256];
__device__ __half g_We2T1[128 * 128];     // W_eu2^T [n][k]
__device__ __half g_We2T2[128 * 128];

// ---------------- helpers ---------------------------------------------------
__device__ __forceinline__ uint32_t smem_u32(const void* p) {
    uint32_t a;
    asm("{ .reg .u64 t; cvta.to.shared.u64 t, %1; cvt.u32.u64 %0, t; }"
        : "=r"(a) : "l"(p));
    return a;
}
#define LDSM4(r, addr) \
    asm volatile("ldmatrix.sync.aligned.m8n8.x4.shared.b16 {%0,%1,%2,%3}, [%4];" \
        : "=r"((r)[0]), "=r"((r)[1]), "=r"((r)[2]), "=r"((r)[3]) : "r"(addr))
#define MMA_F16(C, A, b0, b1) \
    asm volatile("mma.sync.aligned.m16n8k16.row.col.f32.f16.f16.f32 " \
        "{%0,%1,%2,%3},{%4,%5,%6,%7},{%8,%9},{%0,%1,%2,%3};" \
        : "+f"((C)[0]), "+f"((C)[1]), "+f"((C)[2]), "+f"((C)[3]) \
        : "r"((A)[0]), "r"((A)[1]), "r"((A)[2]), "r"((A)[3]), "r"(b0), "r"(b1))
#define CP_ASYNC16(dst, src) \
    asm volatile("cp.async.ca.shared.global [%0], [%1], 16;" :: "r"(dst), "l"(src))
#define CP_COMMIT() asm volatile("cp.async.commit_group;")
#define CP_WAIT_ALL() asm volatile("cp.async.wait_all;")

__device__ __forceinline__ void split16(float v, __half& a, __half& b) {
    a = __float2half(v);
    b = __float2half(v - __half2float(a));
}

// ---------------- K1: h = relu(node_feats @ W_p + b_p) + limbs -------------
__global__ void k_proj_nodes(const float* __restrict__ nf,
                             const float* __restrict__ Wp,
                             const float* __restrict__ bp) {
    __shared__ float s[4 * 64];
    int tid = threadIdx.x;
    int n0 = blockIdx.x * 4;
    s[tid] = nf[(size_t)n0 * 64 + tid];
    __syncthreads();
    int nl = tid >> 6, c = tid & 63;
    float sum = bp[c];
#pragma unroll 16
    for (int k = 0; k < 64; k++) sum += s[nl * 64 + k] * Wp[k * 64 + c];
    float v = fmaxf(sum, 0.f);
    size_t o = (size_t)(n0 + nl) * 64 + c;
    g_h[o] = v;
    __half a, b; split16(v, a, b);
    g_h1[o] = a; g_h2[o] = b;
}

// ---------------- K2: e = relu(edge_attr @ W_pe + b_pe) + limbs ------------
__global__ void k_proj_edges(const float* __restrict__ ea,
                             const float* __restrict__ Wpe,
                             const float* __restrict__ bpe) {
    __shared__ float s[2 * 16];
    int tid = threadIdx.x;
    int e0 = blockIdx.x * 2;
    if (tid < 32) s[tid] = ea[(size_t)e0 * 16 + tid];
    __syncthreads();
    int el = tid >> 7, c = tid & 127;
    float sum = bpe[c];
#pragma unroll
    for (int k = 0; k < 16; k++) sum += s[el * 16 + k] * Wpe[k * 128 + c];
    float v = fmaxf(sum, 0.f);
    size_t idx = (size_t)(e0 + el) * 128 + c;
    g_e[idx] = v;
    __half a, b; split16(v, a, b);
    g_e1[idx] = a; g_e2[idx] = b;
}

// ---------------- weight transpose + fp16 2-limb split ---------------------
// W: [K][N] row-major -> dst[n*K + k], sel chooses destination globals.
__global__ void k_split_t(const float* __restrict__ W, int K, int N, int sel) {
    __shared__ float t[32][33];
    int x = threadIdx.x, y = threadIdx.y;           // 32 x 8
    int nb = blockIdx.x * 32, kb = blockIdx.y * 32;
#pragma unroll
    for (int i = 0; i < 4; i++)
        t[y + 8 * i][x] = W[(size_t)(kb + y + 8 * i) * N + nb + x];
    __syncthreads();
    __half* d1 = (sel == 0) ? g_Wt1 : (sel == 1) ? g_We1T1 : g_We2T1;
    __half* d2 = (sel == 0) ? g_Wt2 : (sel == 1) ? g_We1T2 : g_We2T2;
#pragma unroll
    for (int i = 0; i < 4; i++) {
        float v = t[x][y + 8 * i];
        size_t o = (size_t)(nb + y + 8 * i) * K + kb + x;
        __half a, b; split16(v, a, b);
        d1[o] = a; d2[o] = b;
    }
}

// ---------------- zero agg -------------------------------------------------
__global__ void k_zero() {
    int idx = blockIdx.x * blockDim.x + threadIdx.x;
    for (int i = idx; i < N_NODES * DIM; i += gridDim.x * blockDim.x)
        g_agg[i] = 0.f;
}

// ---------------- K4: NNConv, fp16 2-pass mma ------------------------------
// CTA = 128 edges, 8 warps. A = e1 (single fp16 limb) in regs for all 64 d.
// Per d: B tile = W^T chunk [64n][128k] x {W1,W2 limbs}, cp.async dbl-buffered.
// 2 MMAs per (kf,nf): e1*W1 + e1*W2.  Epilogue: +bias, relu, *h_src, msg acc.
#define NC_SMEM 120832
#define OFF_BIAS 1024
#define OFF_HS   17408
#define OFF_AB   51200
extern "C" __global__ void __launch_bounds__(256, 1)
k_nnconv_mma(const int* __restrict__ eidx, const float* __restrict__ b_nn) {
    extern __shared__ char sm[];
    int* sc = (int*)sm;
    int* tcs = (int*)(sm + 512);
    float* sbias = (float*)(sm + OFF_BIAS);
    float* hs = (float*)(sm + OFF_HS);
    char* AB = sm + OFF_AB;
    const uint32_t ABu = smem_u32(AB);

    const int tid = threadIdx.x;
    const int e0 = blockIdx.x * 128;
    const int w = tid >> 5, lane = tid & 31;

    if (tid < 128) sc[tid] = eidx[e0 + tid];
    else           tcs[tid - 128] = eidx[N_EDGES + e0 + (tid - 128)];
#pragma unroll
    for (int i = 0; i < 4; i++)
        ((float4*)sbias)[i * 256 + tid] = ((const float4*)b_nn)[i * 256 + tid];
    __syncthreads();

    // gathered h[src] -> hs (stride 65 floats)
    {
        int l = tid >> 1, d0 = (tid & 1) * 32;
        const float* hrow = g_h + (size_t)sc[l] * 64 + d0;
        float* dst = hs + l * 65 + d0;
#pragma unroll
        for (int i = 0; i < 32; i += 4) {
            float4 v = *(const float4*)(hrow + i);
            dst[i] = v.x; dst[i + 1] = v.y; dst[i + 2] = v.z; dst[i + 3] = v.w;
        }
    }
    // A staging: e1 rows (256B) -> stride-272 smem
    {
        const uint4* s1 = (const uint4*)(g_e1 + (size_t)e0 * 128);
#pragma unroll
        for (int it = 0; it < 8; it++) {
            int idx = it * 256 + tid;
            int row = idx >> 4, sl = idx & 15;
            *(uint4*)(AB + row * 272 + sl * 16) = s1[row * 16 + sl];
        }
    }
    __syncthreads();

    // A fragments (persistent): a1[kf][4]
    uint32_t a1[8][4];
    {
        uint32_t base = ABu + (uint32_t)((16 * w + (lane & 15)) * 272 +
                                         (lane >> 4) * 16);
#pragma unroll
        for (int kf = 0; kf < 8; kf++) LDSM4(a1[kf], base + kf * 32);
    }
    __syncthreads();   // AB becomes the B double-buffer

    // B(0) -> buf 0  (plane0 = W1, plane1 = W2, plane stride 17408)
    for (int i = tid; i < 2176; i += 256) {
        int row = i / 17, sl = i - row * 17;
        if (sl < 16) {
            int plane = row >> 6, n = row & 63;
            const __half* gsrc = (plane ? g_Wt2 : g_Wt1) + (size_t)n * 128 + sl * 8;
            CP_ASYNC16(ABu + plane * 17408 + n * 272 + sl * 16, gsrc);
        }
    }
    CP_COMMIT();

    const int gid = lane >> 2, tpair = (lane & 3) * 2;
    const int row0 = 16 * w + gid;
    const float* hvp0 = hs + row0 * 65;
    const float* hvp1 = hs + (row0 + 8) * 65;
    const uint32_t boff = (uint32_t)((lane >> 4) * 17408 + (lane & 7) * 272 +
                                     ((lane >> 3) & 1) * 16);
    float msg[8][4] = {};

    for (int d = 0; d < 64; d++) {
        CP_WAIT_ALL();
        __syncthreads();
        if (d + 1 < 64) {
            uint32_t dstu = ABu + ((d + 1) & 1) * 34816;
            for (int i = tid; i < 2176; i += 256) {
                int row = i / 17, sl = i - row * 17;
                if (sl < 16) {
                    int plane = row >> 6, n = row & 63;
                    const __half* gsrc = (plane ? g_Wt2 : g_Wt1) +
                        ((size_t)(d + 1) * 64 + n) * 128 + sl * 8;
                    CP_ASYNC16(dstu + plane * 17408 + n * 272 + sl * 16, gsrc);
                }
            }
            CP_COMMIT();
        }

        float C[8][4];
        const float* bptr = sbias + d * 64 + tpair;
#pragma unroll
        for (int nf = 0; nf < 8; nf++) {
            float2 bv = *(const float2*)(bptr + nf * 8);
            C[nf][0] = bv.x; C[nf][1] = bv.y;
            C[nf][2] = bv.x; C[nf][3] = bv.y;
        }
        const uint32_t bb = ABu + (d & 1) * 34816 + boff;
#pragma unroll
        for (int kf = 0; kf < 8; kf++) {
#pragma unroll
            for (int nf = 0; nf < 8; nf++) {
                uint32_t b[4];
                LDSM4(b, bb + nf * 2176 + kf * 32);
                MMA_F16(C[nf], a1[kf], b[0], b[1]);   // e1 * W1
                MMA_F16(C[nf], a1[kf], b[2], b[3]);   // e1 * W2
            }
        }
        float hv0 = hvp0[d], hv1 = hvp1[d];
#pragma unroll
        for (int nf = 0; nf < 8; nf++) {
            msg[nf][0] = fmaf(hv0, fmaxf(C[nf][0], 0.f), msg[nf][0]);
            msg[nf][1] = fmaf(hv0, fmaxf(C[nf][1], 0.f), msg[nf][1]);
            msg[nf][2] = fmaf(hv1, fmaxf(C[nf][2], 0.f), msg[nf][2]);
            msg[nf][3] = fmaf(hv1, fmaxf(C[nf][3], 0.f), msg[nf][3]);
        }
    }

    float* d0 = g_agg + (size_t)tcs[row0] * 64 + tpair;
    float* d1 = g_agg + (size_t)tcs[row0 + 8] * 64 + tpair;
#pragma unroll
    for (int nf = 0; nf < 8; nf++) {
        atomicAdd(d0 + nf * 8,     msg[nf][0]);
        atomicAdd(d0 + nf * 8 + 1, msg[nf][1]);
        atomicAdd(d1 + nf * 8,     msg[nf][2]);
        atomicAdd(d1 + nf * 8 + 1, msg[nf][3]);
    }
}

// ---------------- K5: m = relu(agg + h @ W_root + b_conv) ------------------
__global__ void k_conv(const float* __restrict__ Wr,
                       const float* __restrict__ bc) {
    __shared__ float s[4 * 64];
    int tid = threadIdx.x;
    int n0 = blockIdx.x * 4;
    s[tid] = g_h[(size_t)n0 * 64 + tid];
    __syncthreads();
    int nl = tid >> 6, c = tid & 63;
    float sum = bc[c] + g_agg[(size_t)(n0 + nl) * 64 + c];
#pragma unroll 16
    for (int k = 0; k < 64; k++) sum += s[nl * 64 + k] * Wr[k * 64 + c];
    g_m[(size_t)(n0 + nl) * 64 + c] = fmaxf(sum, 0.f);
}

// ---------------- K6: fused GRU cell (+ h limbs) ---------------------------
__global__ void k_gru(const float* __restrict__ wih,
                      const float* __restrict__ whh,
                      const float* __restrict__ bih,
                      const float* __restrict__ bhh) {
    __shared__ float mr[64], hr[64], gi[192], gh[192];
    int n = blockIdx.x;
    int c = threadIdx.x;
    if (c < 64) {
        mr[c] = g_m[(size_t)n * 64 + c];
        hr[c] = g_h[(size_t)n * 64 + c];
    }
    __syncthreads();
    float si = bih[c], sh = bhh[c];
#pragma unroll 16
    for (int k = 0; k < 64; k++) {
        si += mr[k] * wih[k * 192 + c];
        sh += hr[k] * whh[k * 192 + c];
    }
    gi[c] = si; gh[c] = sh;
    __syncthreads();
    if (c < 64) {
        float r = 1.f / (1.f + expf(-(gi[c] + gh[c])));
        float z = 1.f / (1.f + expf(-(gi[64 + c] + gh[64 + c])));
        float nc = tanhf(gi[128 + c] + r * gh[128 + c]);
        float v = (1.f - z) * nc + z * hr[c];
        size_t o = (size_t)n * 64 + c;
        g_h[o] = v;
        __half a, b; split16(v, a, b);
        g_h1[o] = a; g_h2[o] = b;
    }
}

// ---------------- K7: edge-update MLP on tensor cores (fp16 3-pass) --------
// CTA = 64 edges, 256 thr. Layer1: [64,256]@[256,128]; Layer2: [64,128]@[128,128]
// A limbs a1/a2 (exact to 2^-22), W limbs V1/V2; passes a1V1 + a2V1 + a1V2.
// smem: sc/tc@0(512) b1s@512 b2s@1024
//   A @1536: 2 planes x 64row x 528B (67584)     [t reuses this after L1]
//   B @69120: 2 planes x 128row x 528B (135168)  [B2 reuses: 2 x 128 x 272B]
#define EU_SMEM  204288
#define EU_OFF_A 1536
#define EU_A_PL  33792
#define EU_OFF_B 69120
#define EU_B_PL  67584
#define EU_T_PL  17408
#define EU_B2_PL 34816
extern "C" __global__ void __launch_bounds__(256, 1)
k_edgeup_tc(const int* __restrict__ eidx,
            const float* __restrict__ b1, const float* __restrict__ b2) {
    extern __shared__ char sm[];
    const uint32_t sbase = smem_u32(sm);
    int* sc = (int*)sm;
    int* tcs = (int*)(sm + 256);
    float* b1s = (float*)(sm + 512);
    float* b2s = (float*)(sm + 1024);

    const int tid = threadIdx.x;
    const int e0 = blockIdx.x * 64;
    const int w = tid >> 5, lane = tid & 31;

    if (tid < 64)       sc[tid] = eidx[e0 + tid];
    else if (tid < 128) tcs[tid - 64] = eidx[N_EDGES + e0 + (tid - 64)];
    else if (tid < 256) {
        int c = tid - 128;
        b1s[c] = b1[c];
        b2s[c] = b2[c];
    }

    // B1 (layer-1 weights) via cp.async: 2 planes x 128 rows x 32 chunks
    for (int i = tid; i < 8192; i += 256) {
        int p = i >> 12, j = i & 4095;
        int n = j >> 5, c = j & 31;
        const __half* src = (p ? g_We1T2 : g_We1T1) + (size_t)n * 256 + c * 8;
        CP_ASYNC16(sbase + EU_OFF_B + p * EU_B_PL + n * 528 + c * 16, src);
    }
    CP_COMMIT();
    __syncthreads();

    // A staging: limbs of [h_src | h_tgt | e], rows 528B
    for (int i = tid; i < 1024; i += 256) {           // h sections
        int s = i >> 9, j = i & 511;
        int l = j >> 3, c = (j & 7) * 8;
        int nrow = s ? tcs[l] : sc[l];
        const uint4* s1 = (const uint4*)(g_h1 + (size_t)nrow * 64 + c);
        const uint4* s2 = (const uint4*)(g_h2 + (size_t)nrow * 64 + c);
        char* dst = sm + EU_OFF_A + l * 528 + s * 128 + c * 2;
        *(uint4*)dst = *s1;
        *(uint4*)(dst + EU_A_PL) = *s2;
    }
    for (int i = tid; i < 1024; i += 256) {           // e section
        int l = i >> 4, c = (i & 15) * 8;
        const uint4* s1 = (const uint4*)(g_e1 + (size_t)(e0 + l) * 128 + c);
        const uint4* s2 = (const uint4*)(g_e2 + (size_t)(e0 + l) * 128 + c);
        char* dst = sm + EU_OFF_A + l * 528 + 256 + c * 2;
        *(uint4*)dst = *s1;
        *(uint4*)(dst + EU_A_PL) = *s2;
    }
    CP_WAIT_ALL();
    __syncthreads();

    const int mf = w & 3, nh = w >> 2;
    const int nbase = nh * 64;
    const int gid = lane >> 2, tpair = (lane & 3) * 2;
    const uint32_t aoff = (uint32_t)((16 * mf + (lane & 15)) * 528 + (lane >> 4) * 16);
    const uint32_t boff = (uint32_t)(nbase * 528 + (lane & 7) * 528 +
                                     ((lane >> 3) & 1) * 16 + (lane >> 4) * EU_B_PL);

    // ---- Layer 1 ----
    float C[8][4];
#pragma unroll
    for (int nf = 0; nf < 8; nf++) {
        int col = nbase + nf * 8 + tpair;
        float2 bv = *(const float2*)(b1s + col);
        C[nf][0] = bv.x; C[nf][1] = bv.y;
        C[nf][2] = bv.x; C[nf][3] = bv.y;
    }
#pragma unroll
    for (int kf = 0; kf < 16; kf++) {
        uint32_t fa1[4], fa2[4];
        LDSM4(fa1, sbase + EU_OFF_A + aoff + kf * 32);
        LDSM4(fa2, sbase + EU_OFF_A + EU_A_PL + aoff + kf * 32);
#pragma unroll
        for (int nf = 0; nf < 8; nf++) {
            uint32_t b[4];
            LDSM4(b, sbase + EU_OFF_B + boff + nf * 4224 + kf * 32);
            MMA_F16(C[nf], fa1, b[0], b[1]);    // a1 * V1
            MMA_F16(C[nf], fa2, b[0], b[1]);    // a2 * V1
            MMA_F16(C[nf], fa1, b[2], b[3]);    // a1 * V2
        }
    }
    __syncthreads();   // A and B1 fully consumed

    // B2 via cp.async into B region; t limbs into A region
    for (int i = tid; i < 4096; i += 256) {
        int p = i >> 11;
        int n = (i >> 4) & 127, c = i & 15;
        const __half* src = (p ? g_We2T2 : g_We2T1) + (size_t)n * 128 + c * 8;
        CP_ASYNC16(sbase + EU_OFF_B + p * EU_B2_PL + n * 272 + c * 16, src);
    }
    CP_COMMIT();
    {
        int r0 = 16 * mf + gid;
#pragma unroll
        for (int nf = 0; nf < 8; nf++) {
            int col = nbase + nf * 8 + tpair;
#pragma unroll
            for (int half = 0; half < 2; half++) {
                int r = r0 + half * 8;
                float v0 = fmaxf(C[nf][2 * half], 0.f);
                float v1 = fmaxf(C[nf][2 * half + 1], 0.f);
                __half a0, c0, a1_, c1;
                split16(v0, a0, c0);
                split16(v1, a1_, c1);
                char* base = sm + EU_OFF_A + r * 272 + col * 2;
                *(__half2*)base = __halves2half2(a0, a1_);
                *(__half2*)(base + EU_T_PL) = __halves2half2(c0, c1);
            }
        }
    }
    CP_WAIT_ALL();
    __syncthreads();

    // ---- Layer 2 ----
    const uint32_t toff = (uint32_t)((16 * mf + (lane & 15)) * 272 + (lane >> 4) * 16);
    const uint32_t b2off = (uint32_t)(nbase * 272 + (lane & 7) * 272 +
                                      ((lane >> 3) & 1) * 16 + (lane >> 4) * EU_B2_PL);
    float C2[8][4];
#pragma unroll
    for (int nf = 0; nf < 8; nf++) {
        int col = nbase + nf * 8 + tpair;
        float2 bv = *(const float2*)(b2s + col);
        C2[nf][0] = bv.x; C2[nf][1] = bv.y;
        C2[nf][2] = bv.x; C2[nf][3] = bv.y;
    }
#pragma unroll
    for (int kf = 0; kf < 8; kf++) {
        uint32_t fa1[4], fa2[4];
        LDSM4(fa1, sbase + EU_OFF_A + toff + kf * 32);
        LDSM4(fa2, sbase + EU_OFF_A + EU_T_PL + toff + kf * 32);
#pragma unroll
        for (int nf = 0; nf < 8; nf++) {
            uint32_t b[4];
            LDSM4(b, sbase + EU_OFF_B + b2off + nf * 2176 + kf * 32);
            MMA_F16(C2[nf], fa1, b[0], b[1]);
            MMA_F16(C2[nf], fa2, b[0], b[1]);
            MMA_F16(C2[nf], fa1, b[2], b[3]);
        }
    }

    // output: e_new fp32 + fp16 limbs
    {
        int r0 = 16 * mf + gid;
#pragma unroll
        for (int nf = 0; nf < 8; nf++) {
            int col = nbase + nf * 8 + tpair;
#pragma unroll
            for (int half = 0; half < 2; half++) {
                int r = r0 + half * 8;
                size_t o = (size_t)(e0 + r) * 128 + col;
                float v0 = fmaxf(C2[nf][2 * half], 0.f);
                float v1 = fmaxf(C2[nf][2 * half + 1], 0.f);
                g_e[o] = v0; g_e[o + 1] = v1;
                __half a0, c0, a1_, c1;
                split16(v0, a0, c0);
                split16(v1, a1_, c1);
                *(__half2*)(g_e1 + o) = __halves2half2(a0, a1_);
                *(__half2*)(g_e2 + o) = __halves2half2(c0, c1);
            }
        }
    }
}

// ---------------- output copy ----------------------------------------------
__global__ void k_out(float4* __restrict__ out) {
    const int H4 = (N_NODES * DIM) / 4;
    const int T4 = H4 + (N_EDGES * EHID) / 4;
    int idx = blockIdx.x * blockDim.x + threadIdx.x;
    const float4* h4 = (const float4*)g_h;
    const float4* e4 = (const float4*)g_e;
    for (int i = idx; i < T4; i += gridDim.x * blockDim.x)
        out[i] = (i < H4) ? h4[i] : e4[i - H4];
}

// ---------------- launcher -------------------------------------------------
extern "C" void kernel_launch(void* const* d_in, const int* in_sizes, int n_in,
                              void* d_out, int out_size) {
    const float* nf   = (const float*)d_in[0];
    const float* ea   = (const float*)d_in[1];
    const int*   eidx = (const int*)  d_in[2];
    const float* Wp   = (const float*)d_in[3];
    const float* bp   = (const float*)d_in[4];
    const float* Wpe  = (const float*)d_in[5];
    const float* bpe  = (const float*)d_in[6];
    const float* Wnn  = (const float*)d_in[7];
    const float* bnn  = (const float*)d_in[8];
    const float* Wr   = (const float*)d_in[9];
    const float* bc   = (const float*)d_in[10];
    const float* wih  = (const float*)d_in[11];
    const float* whh  = (const float*)d_in[12];
    const float* bih  = (const float*)d_in[13];
    const float* bhh  = (const float*)d_in[14];
    const float* We1  = (const float*)d_in[15];
    const float* be1  = (const float*)d_in[16];
    const float* We2  = (const float*)d_in[17];
    const float* be2  = (const float*)d_in[18];

    cudaFuncSetAttribute(k_nnconv_mma, cudaFuncAttributeMaxDynamicSharedMemorySize, NC_SMEM);
    cudaFuncSetAttribute(k_edgeup_tc, cudaFuncAttributeMaxDynamicSharedMemorySize, EU_SMEM);

    k_split_t<<<dim3(128, 4), dim3(32, 8)>>>(Wnn, 128, 4096, 0);
    k_split_t<<<dim3(4, 8),   dim3(32, 8)>>>(We1, 256, 128, 1);
    k_split_t<<<dim3(4, 4),   dim3(32, 8)>>>(We2, 128, 128, 2);
    k_proj_nodes<<<N_NODES / 4, 256>>>(nf, Wp, bp);
    k_proj_edges<<<N_EDGES / 2, 256>>>(ea, Wpe, bpe);

    for (int step = 0; step < NUM_STEPS; step++) {
        k_zero<<<256, 256>>>();
        k_nnconv_mma<<<N_EDGES / 128, 256, NC_SMEM>>>(eidx, bnn);
        k_conv<<<N_NODES / 4, 256>>>(Wr, bc);
        k_gru<<<N_NODES, 192>>>(wih, whh, bih, bhh);
        k_edgeup_tc<<<N_EDGES / 64, 256, EU_SMEM>>>(eidx, be1, be2);
    }

    k_out<<<2048, 256>>>((float4*)d_out);
}

// round 5
// speedup vs baseline: 5.2399x; 1.6872x over previous
#include <cuda_runtime.h>
#include <cuda_fp16.h>
#include <math.h>
#include <stdint.h>

#define N_NODES 4096
#define N_EDGES 32768
#define DIM 64
#define EHID 128
#define NUM_STEPS 3

// ---------------- scratch (device globals) ---------------------------------
__device__ float g_h[N_NODES * DIM];
__device__ float g_e[N_EDGES * EHID];
__device__ float g_agg[N_NODES * DIM];
__device__ __half g_h1[N_NODES * DIM];    // fp16 limb1 of h
__device__ __half g_h2[N_NODES * DIM];    // fp16 limb2
__device__ __half g_e1[N_EDGES * EHID];   // fp16 limb1 of e
__device__ __half g_e2[N_EDGES * EHID];   // fp16 limb2
__device__ __half g_Wt1[4096 * 128];      // W_nn^T [n][k] limb1
__device__ __half g_We1T1[128 * 256];     // W_eu1^T [n][k] limb1
__device__ __half g_We1T2[128 * 256];
__device__ __half g_We2T1[128 * 128];     // W_eu2^T [n][k]
__device__ __half g_We2T2[128 * 128];

// ---------------- helpers ---------------------------------------------------
__device__ __forceinline__ uint32_t smem_u32(const void* p) {
    uint32_t a;
    asm("{ .reg .u64 t; cvta.to.shared.u64 t, %1; cvt.u32.u64 %0, t; }"
        : "=r"(a) : "l"(p));
    return a;
}
#define LDSM4(r, addr) \
    asm volatile("ldmatrix.sync.aligned.m8n8.x4.shared.b16 {%0,%1,%2,%3}, [%4];" \
        : "=r"((r)[0]), "=r"((r)[1]), "=r"((r)[2]), "=r"((r)[3]) : "r"(addr))
#define MMA_F16(C, A, b0, b1) \
    asm volatile("mma.sync.aligned.m16n8k16.row.col.f32.f16.f16.f32 " \
        "{%0,%1,%2,%3},{%4,%5,%6,%7},{%8,%9},{%0,%1,%2,%3};" \
        : "+f"((C)[0]), "+f"((C)[1]), "+f"((C)[2]), "+f"((C)[3]) \
        : "r"((A)[0]), "r"((A)[1]), "r"((A)[2]), "r"((A)[3]), "r"(b0), "r"(b1))
#define CP_ASYNC16(dst, src) \
    asm volatile("cp.async.ca.shared.global [%0], [%1], 16;" :: "r"(dst), "l"(src))
#define CP_COMMIT() asm volatile("cp.async.commit_group;")
#define CP_WAIT_ALL() asm volatile("cp.async.wait_all;")

__device__ __forceinline__ void split16(float v, __half& a, __half& b) {
    a = __float2half(v);
    b = __float2half(v - __half2float(a));
}

// ---------------- K1: h = relu(node_feats @ W_p + b_p) + limbs -------------
__global__ void k_proj_nodes(const float* __restrict__ nf,
                             const float* __restrict__ Wp,
                             const float* __restrict__ bp) {
    __shared__ float s[4 * 64];
    int tid = threadIdx.x;
    int n0 = blockIdx.x * 4;
    s[tid] = nf[(size_t)n0 * 64 + tid];
    __syncthreads();
    int nl = tid >> 6, c = tid & 63;
    float sum = bp[c];
#pragma unroll 16
    for (int k = 0; k < 64; k++) sum += s[nl * 64 + k] * Wp[k * 64 + c];
    float v = fmaxf(sum, 0.f);
    size_t o = (size_t)(n0 + nl) * 64 + c;
    g_h[o] = v;
    __half a, b; split16(v, a, b);
    g_h1[o] = a; g_h2[o] = b;
}

// ---------------- K2: e = relu(edge_attr @ W_pe + b_pe) + limbs ------------
__global__ void k_proj_edges(const float* __restrict__ ea,
                             const float* __restrict__ Wpe,
                             const float* __restrict__ bpe) {
    __shared__ float s[2 * 16];
    int tid = threadIdx.x;
    int e0 = blockIdx.x * 2;
    if (tid < 32) s[tid] = ea[(size_t)e0 * 16 + tid];
    __syncthreads();
    int el = tid >> 7, c = tid & 127;
    float sum = bpe[c];
#pragma unroll
    for (int k = 0; k < 16; k++) sum += s[el * 16 + k] * Wpe[k * 128 + c];
    float v = fmaxf(sum, 0.f);
    size_t idx = (size_t)(e0 + el) * 128 + c;
    g_e[idx] = v;
    __half a, b; split16(v, a, b);
    g_e1[idx] = a; g_e2[idx] = b;
}

// ---------------- weight transpose + fp16 limb split -----------------------
// W: [K][N] row-major -> dst[n*K + k]. sel: 0 = W_nn (limb1 only),
// 1 = W_eu1 (2 limbs), 2 = W_eu2 (2 limbs).
__global__ void k_split_t(const float* __restrict__ W, int K, int N, int sel) {
    __shared__ float t[32][33];
    int x = threadIdx.x, y = threadIdx.y;           // 32 x 8
    int nb = blockIdx.x * 32, kb = blockIdx.y * 32;
#pragma unroll
    for (int i = 0; i < 4; i++)
        t[y + 8 * i][x] = W[(size_t)(kb + y + 8 * i) * N + nb + x];
    __syncthreads();
    __half* d1 = (sel == 0) ? g_Wt1 : (sel == 1) ? g_We1T1 : g_We2T1;
    __half* d2 = (sel == 1) ? g_We1T2 : g_We2T2;
#pragma unroll
    for (int i = 0; i < 4; i++) {
        float v = t[x][y + 8 * i];
        size_t o = (size_t)(nb + y + 8 * i) * K + kb + x;
        __half a, b; split16(v, a, b);
        d1[o] = a;
        if (sel != 0) d2[o] = b;
    }
}

// ---------------- zero agg -------------------------------------------------
__global__ void k_zero() {
    int idx = blockIdx.x * blockDim.x + threadIdx.x;
    for (int i = idx; i < N_NODES * DIM; i += gridDim.x * blockDim.x)
        g_agg[i] = 0.f;
}

// ---------------- K4: NNConv, fp16 single-pass mma -------------------------
// CTA = 128 edges, 8 warps, occ 2. A = e1 in regs for all 64 d-chunks.
// Per d: B = W1^T chunk [64n][128k] (17408B rows of 272), cp.async dbl-buf.
// LDSM4 fetches an nf-PAIR (lanes 16-31 -> next n8 group): halves smem traffic.
// smem: sc@0 tc@512 bias@1024(16384) hs@17408(33280) AB@50688(34816) = 85504
#define NC_SMEM 85504
#define OFF_BIAS 1024
#define OFF_HS   17408
#define OFF_AB   50688
extern "C" __global__ void __launch_bounds__(256, 2)
k_nnconv_mma(const int* __restrict__ eidx, const float* __restrict__ b_nn) {
    extern __shared__ char sm[];
    int* sc = (int*)sm;
    int* tcs = (int*)(sm + 512);
    float* sbias = (float*)(sm + OFF_BIAS);
    float* hs = (float*)(sm + OFF_HS);
    char* AB = sm + OFF_AB;
    const uint32_t ABu = smem_u32(AB);

    const int tid = threadIdx.x;
    const int e0 = blockIdx.x * 128;
    const int w = tid >> 5, lane = tid & 31;

    if (tid < 128) sc[tid] = eidx[e0 + tid];
    else           tcs[tid - 128] = eidx[N_EDGES + e0 + (tid - 128)];
#pragma unroll
    for (int i = 0; i < 4; i++)
        ((float4*)sbias)[i * 256 + tid] = ((const float4*)b_nn)[i * 256 + tid];
    __syncthreads();

    // gathered h[src] -> hs (stride 65 floats)
    {
        int l = tid >> 1, d0 = (tid & 1) * 32;
        const float* hrow = g_h + (size_t)sc[l] * 64 + d0;
        float* dst = hs + l * 65 + d0;
#pragma unroll
        for (int i = 0; i < 32; i += 4) {
            float4 v = *(const float4*)(hrow + i);
            dst[i] = v.x; dst[i + 1] = v.y; dst[i + 2] = v.z; dst[i + 3] = v.w;
        }
    }
    // A staging: e1 rows (256B) -> stride-272 smem (fills AB region)
    {
        const uint4* s1 = (const uint4*)(g_e1 + (size_t)e0 * 128);
#pragma unroll
        for (int it = 0; it < 8; it++) {
            int idx = it * 256 + tid;
            int row = idx >> 4, sl = idx & 15;
            *(uint4*)(AB + row * 272 + sl * 16) = s1[row * 16 + sl];
        }
    }
    __syncthreads();

    // A fragments (persistent): a1[kf][4]
    uint32_t a1[8][4];
    {
        uint32_t base = ABu + (uint32_t)((16 * w + (lane & 15)) * 272 +
                                         (lane >> 4) * 16);
#pragma unroll
        for (int kf = 0; kf < 8; kf++) LDSM4(a1[kf], base + kf * 32);
    }
    __syncthreads();   // AB becomes the B double-buffer (2 x 17408)

    // B(0) -> buf 0  (64 rows x 272B)
    for (int i = tid; i < 1088; i += 256) {
        int row = i / 17, sl = i - row * 17;
        if (sl < 16) {
            const __half* gsrc = g_Wt1 + (size_t)row * 128 + sl * 8;
            CP_ASYNC16(ABu + row * 272 + sl * 16, gsrc);
        }
    }
    CP_COMMIT();

    const int gid = lane >> 2, tpair = (lane & 3) * 2;
    const int row0 = 16 * w + gid;
    const float* hvp0 = hs + row0 * 65;
    const float* hvp1 = hs + (row0 + 8) * 65;
    // nf-pair LDSM: lanes 0-15 -> n8 group (2*nfp), lanes 16-31 -> (2*nfp+1)
    const uint32_t boff = (uint32_t)((lane & 7) * 272 + ((lane >> 3) & 1) * 16 +
                                     (lane >> 4) * 2176);
    float msg[8][4] = {};

    for (int d = 0; d < 64; d++) {
        CP_WAIT_ALL();
        __syncthreads();
        if (d + 1 < 64) {
            uint32_t dstu = ABu + ((d + 1) & 1) * 17408;
            for (int i = tid; i < 1088; i += 256) {
                int row = i / 17, sl = i - row * 17;
                if (sl < 16) {
                    const __half* gsrc = g_Wt1 +
                        ((size_t)(d + 1) * 64 + row) * 128 + sl * 8;
                    CP_ASYNC16(dstu + row * 272 + sl * 16, gsrc);
                }
            }
            CP_COMMIT();
        }

        float C[8][4];
        const float* bptr = sbias + d * 64 + tpair;
#pragma unroll
        for (int nf = 0; nf < 8; nf++) {
            float2 bv = *(const float2*)(bptr + nf * 8);
            C[nf][0] = bv.x; C[nf][1] = bv.y;
            C[nf][2] = bv.x; C[nf][3] = bv.y;
        }
        const uint32_t bb = ABu + (d & 1) * 17408 + boff;
#pragma unroll
        for (int kf = 0; kf < 8; kf++) {
#pragma unroll
            for (int nfp = 0; nfp < 4; nfp++) {
                uint32_t b[4];
                LDSM4(b, bb + nfp * 4352 + kf * 32);
                MMA_F16(C[2 * nfp],     a1[kf], b[0], b[1]);
                MMA_F16(C[2 * nfp + 1], a1[kf], b[2], b[3]);
            }
        }
        float hv0 = hvp0[d], hv1 = hvp1[d];
#pragma unroll
        for (int nf = 0; nf < 8; nf++) {
            msg[nf][0] = fmaf(hv0, fmaxf(C[nf][0], 0.f), msg[nf][0]);
            msg[nf][1] = fmaf(hv0, fmaxf(C[nf][1], 0.f), msg[nf][1]);
            msg[nf][2] = fmaf(hv1, fmaxf(C[nf][2], 0.f), msg[nf][2]);
            msg[nf][3] = fmaf(hv1, fmaxf(C[nf][3], 0.f), msg[nf][3]);
        }
    }

    float* d0 = g_agg + (size_t)tcs[row0] * 64 + tpair;
    float* d1 = g_agg + (size_t)tcs[row0 + 8] * 64 + tpair;
#pragma unroll
    for (int nf = 0; nf < 8; nf++) {
        atomicAdd(d0 + nf * 8,     msg[nf][0]);
        atomicAdd(d0 + nf * 8 + 1, msg[nf][1]);
        atomicAdd(d1 + nf * 8,     msg[nf][2]);
        atomicAdd(d1 + nf * 8 + 1, msg[nf][3]);
    }
}

// ---------------- K5+K6 fused: conv + GRU ----------------------------------
__global__ void k_conv_gru(const float* __restrict__ Wr,
                           const float* __restrict__ bc,
                           const float* __restrict__ wih,
                           const float* __restrict__ whh,
                           const float* __restrict__ bih,
                           const float* __restrict__ bhh) {
    __shared__ float hr[64], mm[64], gi[192], gh[192];
    int n = blockIdx.x;
    int c = threadIdx.x;   // 0..191
    if (c < 64) hr[c] = g_h[(size_t)n * 64 + c];
    __syncthreads();
    if (c < 64) {
        float s = bc[c] + g_agg[(size_t)n * 64 + c];
#pragma unroll 16
        for (int k = 0; k < 64; k++) s += hr[k] * Wr[k * 64 + c];
        mm[c] = fmaxf(s, 0.f);
    }
    __syncthreads();
    float si = bih[c], sh = bhh[c];
#pragma unroll 16
    for (int k = 0; k < 64; k++) {
        si += mm[k] * wih[k * 192 + c];
        sh += hr[k] * whh[k * 192 + c];
    }
    gi[c] = si; gh[c] = sh;
    __syncthreads();
    if (c < 64) {
        float r = 1.f / (1.f + expf(-(gi[c] + gh[c])));
        float z = 1.f / (1.f + expf(-(gi[64 + c] + gh[64 + c])));
        float nc = tanhf(gi[128 + c] + r * gh[128 + c]);
        float v = (1.f - z) * nc + z * hr[c];
        size_t o = (size_t)n * 64 + c;
        g_h[o] = v;
        __half a, b; split16(v, a, b);
        g_h1[o] = a; g_h2[o] = b;
    }
}

// ---------------- K7: edge-update MLP on tensor cores (fp16 3-pass) --------
#define EU_SMEM  204288
#define EU_OFF_A 1536
#define EU_A_PL  33792
#define EU_OFF_B 69120
#define EU_B_PL  67584
#define EU_T_PL  17408
#define EU_B2_PL 34816
extern "C" __global__ void __launch_bounds__(256, 1)
k_edgeup_tc(const int* __restrict__ eidx,
            const float* __restrict__ b1, const float* __restrict__ b2) {
    extern __shared__ char sm[];
    const uint32_t sbase = smem_u32(sm);
    int* sc = (int*)sm;
    int* tcs = (int*)(sm + 256);
    float* b1s = (float*)(sm + 512);
    float* b2s = (float*)(sm + 1024);

    const int tid = threadIdx.x;
    const int e0 = blockIdx.x * 64;
    const int w = tid >> 5, lane = tid & 31;

    if (tid < 64)       sc[tid] = eidx[e0 + tid];
    else if (tid < 128) tcs[tid - 64] = eidx[N_EDGES + e0 + (tid - 64)];
    else if (tid < 256) {
        int c = tid - 128;
        b1s[c] = b1[c];
        b2s[c] = b2[c];
    }

    // B1 (layer-1 weights) via cp.async: 2 planes x 128 rows x 32 chunks
    for (int i = tid; i < 8192; i += 256) {
        int p = i >> 12, j = i & 4095;
        int n = j >> 5, c = j & 31;
        const __half* src = (p ? g_We1T2 : g_We1T1) + (size_t)n * 256 + c * 8;
        CP_ASYNC16(sbase + EU_OFF_B + p * EU_B_PL + n * 528 + c * 16, src);
    }
    CP_COMMIT();
    __syncthreads();

    // A staging: limbs of [h_src | h_tgt | e], rows 528B
    for (int i = tid; i < 1024; i += 256) {           // h sections
        int s = i >> 9, j = i & 511;
        int l = j >> 3, c = (j & 7) * 8;
        int nrow = s ? tcs[l] : sc[l];
        const uint4* s1 = (const uint4*)(g_h1 + (size_t)nrow * 64 + c);
        const uint4* s2 = (const uint4*)(g_h2 + (size_t)nrow * 64 + c);
        char* dst = sm + EU_OFF_A + l * 528 + s * 128 + c * 2;
        *(uint4*)dst = *s1;
        *(uint4*)(dst + EU_A_PL) = *s2;
    }
    for (int i = tid; i < 1024; i += 256) {           // e section
        int l = i >> 4, c = (i & 15) * 8;
        const uint4* s1 = (const uint4*)(g_e1 + (size_t)(e0 + l) * 128 + c);
        const uint4* s2 = (const uint4*)(g_e2 + (size_t)(e0 + l) * 128 + c);
        char* dst = sm + EU_OFF_A + l * 528 + 256 + c * 2;
        *(uint4*)dst = *s1;
        *(uint4*)(dst + EU_A_PL) = *s2;
    }
    CP_WAIT_ALL();
    __syncthreads();

    const int mf = w & 3, nh = w >> 2;
    const int nbase = nh * 64;
    const int gid = lane >> 2, tpair = (lane & 3) * 2;
    const uint32_t aoff = (uint32_t)((16 * mf + (lane & 15)) * 528 + (lane >> 4) * 16);
    const uint32_t boff = (uint32_t)(nbase * 528 + (lane & 7) * 528 +
                                     ((lane >> 3) & 1) * 16 + (lane >> 4) * EU_B_PL);

    // ---- Layer 1 ----
    float C[8][4];
#pragma unroll
    for (int nf = 0; nf < 8; nf++) {
        int col = nbase + nf * 8 + tpair;
        float2 bv = *(const float2*)(b1s + col);
        C[nf][0] = bv.x; C[nf][1] = bv.y;
        C[nf][2] = bv.x; C[nf][3] = bv.y;
    }
#pragma unroll
    for (int kf = 0; kf < 16; kf++) {
        uint32_t fa1[4], fa2[4];
        LDSM4(fa1, sbase + EU_OFF_A + aoff + kf * 32);
        LDSM4(fa2, sbase + EU_OFF_A + EU_A_PL + aoff + kf * 32);
#pragma unroll
        for (int nf = 0; nf < 8; nf++) {
            uint32_t b[4];
            LDSM4(b, sbase + EU_OFF_B + boff + nf * 4224 + kf * 32);
            MMA_F16(C[nf], fa1, b[0], b[1]);    // a1 * V1
            MMA_F16(C[nf], fa2, b[0], b[1]);    // a2 * V1
            MMA_F16(C[nf], fa1, b[2], b[3]);    // a1 * V2
        }
    }
    __syncthreads();   // A and B1 fully consumed

    // B2 via cp.async into B region; t limbs into A region
    for (int i = tid; i < 4096; i += 256) {
        int p = i >> 11;
        int n = (i >> 4) & 127, c = i & 15;
        const __half* src = (p ? g_We2T2 : g_We2T1) + (size_t)n * 128 + c * 8;
        CP_ASYNC16(sbase + EU_OFF_B + p * EU_B2_PL + n * 272 + c * 16, src);
    }
    CP_COMMIT();
    {
        int r0 = 16 * mf + gid;
#pragma unroll
        for (int nf = 0; nf < 8; nf++) {
            int col = nbase + nf * 8 + tpair;
#pragma unroll
            for (int half = 0; half < 2; half++) {
                int r = r0 + half * 8;
                float v0 = fmaxf(C[nf][2 * half], 0.f);
                float v1 = fmaxf(C[nf][2 * half + 1], 0.f);
                __half a0, c0, a1_, c1;
                split16(v0, a0, c0);
                split16(v1, a1_, c1);
                char* base = sm + EU_OFF_A + r * 272 + col * 2;
                *(__half2*)base = __halves2half2(a0, a1_);
                *(__half2*)(base + EU_T_PL) = __halves2half2(c0, c1);
            }
        }
    }
    CP_WAIT_ALL();
    __syncthreads();

    // ---- Layer 2 ----
    const uint32_t toff = (uint32_t)((16 * mf + (lane & 15)) * 272 + (lane >> 4) * 16);
    const uint32_t b2off = (uint32_t)(nbase * 272 + (lane & 7) * 272 +
                                      ((lane >> 3) & 1) * 16 + (lane >> 4) * EU_B2_PL);
    float C2[8][4];
#pragma unroll
    for (int nf = 0; nf < 8; nf++) {
        int col = nbase + nf * 8 + tpair;
        float2 bv = *(const float2*)(b2s + col);
        C2[nf][0] = bv.x; C2[nf][1] = bv.y;
        C2[nf][2] = bv.x; C2[nf][3] = bv.y;
    }
#pragma unroll
    for (int kf = 0; kf < 8; kf++) {
        uint32_t fa1[4], fa2[4];
        LDSM4(fa1, sbase + EU_OFF_A + toff + kf * 32);
        LDSM4(fa2, sbase + EU_OFF_A + EU_T_PL + toff + kf * 32);
#pragma unroll
        for (int nf = 0; nf < 8; nf++) {
            uint32_t b[4];
            LDSM4(b, sbase + EU_OFF_B + b2off + nf * 2176 + kf * 32);
            MMA_F16(C2[nf], fa1, b[0], b[1]);
            MMA_F16(C2[nf], fa2, b[0], b[1]);
            MMA_F16(C2[nf], fa1, b[2], b[3]);
        }
    }

    // output: e_new fp32 + fp16 limbs
    {
        int r0 = 16 * mf + gid;
#pragma unroll
        for (int nf = 0; nf < 8; nf++) {
            int col = nbase + nf * 8 + tpair;
#pragma unroll
            for (int half = 0; half < 2; half++) {
                int r = r0 + half * 8;
                size_t o = (size_t)(e0 + r) * 128 + col;
                float v0 = fmaxf(C2[nf][2 * half], 0.f);
                float v1 = fmaxf(C2[nf][2 * half + 1], 0.f);
                g_e[o] = v0; g_e[o + 1] = v1;
                __half a0, c0, a1_, c1;
                split16(v0, a0, c0);
                split16(v1, a1_, c1);
                *(__half2*)(g_e1 + o) = __halves2half2(a0, a1_);
                *(__half2*)(g_e2 + o) = __halves2half2(c0, c1);
            }
        }
    }
}

// ---------------- output copy ----------------------------------------------
__global__ void k_out(float4* __restrict__ out) {
    const int H4 = (N_NODES * DIM) / 4;
    const int T4 = H4 + (N_EDGES * EHID) / 4;
    int idx = blockIdx.x * blockDim.x + threadIdx.x;
    const float4* h4 = (const float4*)g_h;
    const float4* e4 = (const float4*)g_e;
    for (int i = idx; i < T4; i += gridDim.x * blockDim.x)
        out[i] = (i < H4) ? h4[i] : e4[i - H4];
}

// ---------------- launcher -------------------------------------------------
extern "C" void kernel_launch(void* const* d_in, const int* in_sizes, int n_in,
                              void* d_out, int out_size) {
    const float* nf   = (const float*)d_in[0];
    const float* ea   = (const float*)d_in[1];
    const int*   eidx = (const int*)  d_in[2];
    const float* Wp   = (const float*)d_in[3];
    const float* bp   = (const float*)d_in[4];
    const float* Wpe  = (const float*)d_in[5];
    const float* bpe  = (const float*)d_in[6];
    const float* Wnn  = (const float*)d_in[7];
    const float* bnn  = (const float*)d_in[8];
    const float* Wr   = (const float*)d_in[9];
    const float* bc   = (const float*)d_in[10];
    const float* wih  = (const float*)d_in[11];
    const float* whh  = (const float*)d_in[12];
    const float* bih  = (const float*)d_in[13];
    const float* bhh  = (const float*)d_in[14];
    const float* We1  = (const float*)d_in[15];
    const float* be1  = (const float*)d_in[16];
    const float* We2  = (const float*)d_in[17];
    const float* be2  = (const float*)d_in[18];

    cudaFuncSetAttribute(k_nnconv_mma, cudaFuncAttributeMaxDynamicSharedMemorySize, NC_SMEM);
    cudaFuncSetAttribute(k_edgeup_tc, cudaFuncAttributeMaxDynamicSharedMemorySize, EU_SMEM);

    k_split_t<<<dim3(128, 4), dim3(32, 8)>>>(Wnn, 128, 4096, 0);
    k_split_t<<<dim3(4, 8),   dim3(32, 8)>>>(We1, 256, 128, 1);
    k_split_t<<<dim3(4, 4),   dim3(32, 8)>>>(We2, 128, 128, 2);
    k_proj_nodes<<<N_NODES / 4, 256>>>(nf, Wp, bp);
    k_proj_edges<<<N_EDGES / 2, 256>>>(ea, Wpe, bpe);

    for (int step = 0; step < NUM_STEPS; step++) {
        k_zero<<<256, 256>>>();
        k_nnconv_mma<<<N_EDGES / 128, 256, NC_SMEM>>>(eidx, bnn);
        k_conv_gru<<<N_NODES, 192>>>(Wr, bc, wih, whh, bih, bhh);
        k_edgeup_tc<<<N_EDGES / 64, 256, EU_SMEM>>>(eidx, be1, be2);
    }

    k_out<<<2048, 256>>>((float4*)d_out);
}

// round 6
// speedup vs baseline: 5.3979x; 1.0301x over previous
#include <cuda_runtime.h>
#include <cuda_fp16.h>
#include <math.h>
#include <stdint.h>

#define N_NODES 4096
#define N_EDGES 32768
#define DIM 64
#define EHID 128
#define NUM_STEPS 3

// ---------------- scratch (device globals; zero-initialized) ----------------
__device__ float g_h[N_NODES * DIM];
__device__ float g_e[N_EDGES * EHID];
__device__ float g_agg[N_NODES * DIM];    // invariant: zero at kernel_launch entry
__device__ __half g_h1[N_NODES * DIM];
__device__ __half g_h2[N_NODES * DIM];
__device__ __half g_e1[N_EDGES * EHID];
__device__ __half g_e2[N_EDGES * EHID];
__device__ __half g_Wt1[4096 * 128];      // W_nn^T [n][k] limb1
__device__ __half g_We1T1[128 * 256];
__device__ __half g_We1T2[128 * 256];
__device__ __half g_We2T1[128 * 128];
__device__ __half g_We2T2[128 * 128];

// ---------------- helpers ---------------------------------------------------
__device__ __forceinline__ uint32_t smem_u32(const void* p) {
    uint32_t a;
    asm("{ .reg .u64 t; cvta.to.shared.u64 t, %1; cvt.u32.u64 %0, t; }"
        : "=r"(a) : "l"(p));
    return a;
}
#define LDSM4(r, addr) \
    asm volatile("ldmatrix.sync.aligned.m8n8.x4.shared.b16 {%0,%1,%2,%3}, [%4];" \
        : "=r"((r)[0]), "=r"((r)[1]), "=r"((r)[2]), "=r"((r)[3]) : "r"(addr))
#define MMA_F16(C, A, b0, b1) \
    asm volatile("mma.sync.aligned.m16n8k16.row.col.f32.f16.f16.f32 " \
        "{%0,%1,%2,%3},{%4,%5,%6,%7},{%8,%9},{%0,%1,%2,%3};" \
        : "+f"((C)[0]), "+f"((C)[1]), "+f"((C)[2]), "+f"((C)[3]) \
        : "r"((A)[0]), "r"((A)[1]), "r"((A)[2]), "r"((A)[3]), "r"(b0), "r"(b1))
#define CP_ASYNC16(dst, src) \
    asm volatile("cp.async.ca.shared.global [%0], [%1], 16;" :: "r"(dst), "l"(src))
#define CP_COMMIT() asm volatile("cp.async.commit_group;")
#define CP_WAIT_ALL() asm volatile("cp.async.wait_all;")

__device__ __forceinline__ void split16(float v, __half& a, __half& b) {
    a = __float2half(v);
    b = __float2half(v - __half2float(a));
}

// ---------------- K1: h = relu(node_feats @ W_p + b_p) + limbs -------------
__global__ void k_proj_nodes(const float* __restrict__ nf,
                             const float* __restrict__ Wp,
                             const float* __restrict__ bp) {
    __shared__ float s[4 * 64];
    int tid = threadIdx.x;
    int n0 = blockIdx.x * 4;
    s[tid] = nf[(size_t)n0 * 64 + tid];
    __syncthreads();
    int nl = tid >> 6, c = tid & 63;
    float sum = bp[c];
#pragma unroll 16
    for (int k = 0; k < 64; k++) sum += s[nl * 64 + k] * Wp[k * 64 + c];
    float v = fmaxf(sum, 0.f);
    size_t o = (size_t)(n0 + nl) * 64 + c;
    g_h[o] = v;
    __half a, b; split16(v, a, b);
    g_h1[o] = a; g_h2[o] = b;
}

// ---------------- K2: e = relu(edge_attr @ W_pe + b_pe) + limbs ------------
__global__ void k_proj_edges(const float* __restrict__ ea,
                             const float* __restrict__ Wpe,
                             const float* __restrict__ bpe) {
    __shared__ float s[2 * 16];
    int tid = threadIdx.x;
    int e0 = blockIdx.x * 2;
    if (tid < 32) s[tid] = ea[(size_t)e0 * 16 + tid];
    __syncthreads();
    int el = tid >> 7, c = tid & 127;
    float sum = bpe[c];
#pragma unroll
    for (int k = 0; k < 16; k++) sum += s[el * 16 + k] * Wpe[k * 128 + c];
    float v = fmaxf(sum, 0.f);
    size_t idx = (size_t)(e0 + el) * 128 + c;
    g_e[idx] = v;
    __half a, b; split16(v, a, b);
    g_e1[idx] = a; g_e2[idx] = b;
}

// ---------------- weight transpose + fp16 limb split -----------------------
__global__ void k_split_t(const float* __restrict__ W, int K, int N, int sel) {
    __shared__ float t[32][33];
    int x = threadIdx.x, y = threadIdx.y;           // 32 x 8
    int nb = blockIdx.x * 32, kb = blockIdx.y * 32;
#pragma unroll
    for (int i = 0; i < 4; i++)
        t[y + 8 * i][x] = W[(size_t)(kb + y + 8 * i) * N + nb + x];
    __syncthreads();
    __half* d1 = (sel == 0) ? g_Wt1 : (sel == 1) ? g_We1T1 : g_We2T1;
    __half* d2 = (sel == 1) ? g_We1T2 : g_We2T2;
#pragma unroll
    for (int i = 0; i < 4; i++) {
        float v = t[x][y + 8 * i];
        size_t o = (size_t)(nb + y + 8 * i) * K + kb + x;
        __half a, b; split16(v, a, b);
        d1[o] = a;
        if (sel != 0) d2[o] = b;
    }
}

// ---------------- K4: NNConv, fp16 single-pass mma, n-split x4 -------------
// grid 1024: CTA = (128 edges) x (16-col quarter of N). 8 warps, occ 2.
// A = e1 frags in regs for all 64 d. Per d: B = W1^T rows [q*16..q*16+16) of
// chunk d (16 x 272B), cp.async dbl-buffered. nf-pair LDSM: 1 LDSM4 -> 2 MMA.
// smem: sc@0 tc@512 bias@1024(4096) hs@5120(33280) AB@38400(34816) = 73216
#define NC_SMEM 73216
#define OFF_BIAS 1024
#define OFF_HS   5120
#define OFF_AB   38400
extern "C" __global__ void __launch_bounds__(256, 2)
k_nnconv_mma(const int* __restrict__ eidx, const float* __restrict__ b_nn) {
    extern __shared__ char sm[];
    int* sc = (int*)sm;
    int* tcs = (int*)(sm + 512);
    float* sbias = (float*)(sm + OFF_BIAS);
    float* hs = (float*)(sm + OFF_HS);
    char* AB = sm + OFF_AB;
    const uint32_t ABu = smem_u32(AB);

    const int tid = threadIdx.x;
    const int q = blockIdx.x & 3;
    const int e0 = (blockIdx.x >> 2) * 128;
    const int ncol0 = q * 16;
    const int w = tid >> 5, lane = tid & 31;

    if (tid < 128) sc[tid] = eidx[e0 + tid];
    else           tcs[tid - 128] = eidx[N_EDGES + e0 + (tid - 128)];
    // bias quarter: sbias[d*16+j] = b_nn[d*64 + ncol0 + j]
    {
        int d = tid >> 2, jq = tid & 3;
        *(float4*)(sbias + d * 16 + jq * 4) =
            *(const float4*)(b_nn + d * 64 + ncol0 + jq * 4);
    }
    __syncthreads();

    // gathered h[src] -> hs (stride 65 floats)
    {
        int l = tid >> 1, d0 = (tid & 1) * 32;
        const float* hrow = g_h + (size_t)sc[l] * 64 + d0;
        float* dst = hs + l * 65 + d0;
#pragma unroll
        for (int i = 0; i < 32; i += 4) {
            float4 v = *(const float4*)(hrow + i);
            dst[i] = v.x; dst[i + 1] = v.y; dst[i + 2] = v.z; dst[i + 3] = v.w;
        }
    }
    // A staging: e1 rows (256B) -> stride-272 smem
    {
        const uint4* s1 = (const uint4*)(g_e1 + (size_t)e0 * 128);
#pragma unroll
        for (int it = 0; it < 8; it++) {
            int idx = it * 256 + tid;
            int row = idx >> 4, sl = idx & 15;
            *(uint4*)(AB + row * 272 + sl * 16) = s1[row * 16 + sl];
        }
    }
    __syncthreads();

    // A fragments (persistent)
    uint32_t a1[8][4];
    {
        uint32_t base = ABu + (uint32_t)((16 * w + (lane & 15)) * 272 +
                                         (lane >> 4) * 16);
#pragma unroll
        for (int kf = 0; kf < 8; kf++) LDSM4(a1[kf], base + kf * 32);
    }
    __syncthreads();   // AB becomes the B double-buffer (2 x 4352)

    // B(0) -> buf 0: 16 rows x 16 chunks, one cp.async per thread
    {
        int row = tid >> 4, sl = tid & 15;
        CP_ASYNC16(ABu + row * 272 + sl * 16,
                   g_Wt1 + (size_t)(ncol0 + row) * 128 + sl * 8);
    }
    CP_COMMIT();

    const int gid = lane >> 2, tpair = (lane & 3) * 2;
    const int row0 = 16 * w + gid;
    const float* hvp0 = hs + row0 * 65;
    const float* hvp1 = hs + (row0 + 8) * 65;
    // nf-pair: lanes 0-15 -> n8 group 0, lanes 16-31 -> group 1 (stride 2176)
    const uint32_t boff = (uint32_t)((lane & 7) * 272 + ((lane >> 3) & 1) * 16 +
                                     (lane >> 4) * 2176);
    float msg[2][4] = {};

    for (int d = 0; d < 64; d++) {
        CP_WAIT_ALL();
        __syncthreads();
        if (d + 1 < 64) {
            int row = tid >> 4, sl = tid & 15;
            CP_ASYNC16(ABu + ((d + 1) & 1) * 4352 + row * 272 + sl * 16,
                       g_Wt1 + (size_t)((d + 1) * 64 + ncol0 + row) * 128 + sl * 8);
            CP_COMMIT();
        }

        float C[2][4];
        const float* bptr = sbias + d * 16 + tpair;
#pragma unroll
        for (int nf = 0; nf < 2; nf++) {
            float2 bv = *(const float2*)(bptr + nf * 8);
            C[nf][0] = bv.x; C[nf][1] = bv.y;
            C[nf][2] = bv.x; C[nf][3] = bv.y;
        }
        const uint32_t bb = ABu + (d & 1) * 4352 + boff;
#pragma unroll
        for (int kf = 0; kf < 8; kf++) {
            uint32_t b[4];
            LDSM4(b, bb + kf * 32);
            MMA_F16(C[0], a1[kf], b[0], b[1]);
            MMA_F16(C[1], a1[kf], b[2], b[3]);
        }
        float hv0 = hvp0[d], hv1 = hvp1[d];
#pragma unroll
        for (int nf = 0; nf < 2; nf++) {
            msg[nf][0] = fmaf(hv0, fmaxf(C[nf][0], 0.f), msg[nf][0]);
            msg[nf][1] = fmaf(hv0, fmaxf(C[nf][1], 0.f), msg[nf][1]);
            msg[nf][2] = fmaf(hv1, fmaxf(C[nf][2], 0.f), msg[nf][2]);
            msg[nf][3] = fmaf(hv1, fmaxf(C[nf][3], 0.f), msg[nf][3]);
        }
    }

    float* d0 = g_agg + (size_t)tcs[row0] * 64 + ncol0 + tpair;
    float* d1 = g_agg + (size_t)tcs[row0 + 8] * 64 + ncol0 + tpair;
#pragma unroll
    for (int nf = 0; nf < 2; nf++) {
        atomicAdd(d0 + nf * 8,     msg[nf][0]);
        atomicAdd(d0 + nf * 8 + 1, msg[nf][1]);
        atomicAdd(d1 + nf * 8,     msg[nf][2]);
        atomicAdd(d1 + nf * 8 + 1, msg[nf][3]);
    }
}

// ---------------- K5+K6 fused: conv + GRU + agg re-zero --------------------
__global__ void k_conv_gru(const float* __restrict__ Wr,
                           const float* __restrict__ bc,
                           const float* __restrict__ wih,
                           const float* __restrict__ whh,
                           const float* __restrict__ bih,
                           const float* __restrict__ bhh) {
    __shared__ float hr[64], mm[64], gi[192], gh[192];
    int n = blockIdx.x;
    int c = threadIdx.x;   // 0..191
    if (c < 64) hr[c] = g_h[(size_t)n * 64 + c];
    __syncthreads();
    if (c < 64) {
        size_t o = (size_t)n * 64 + c;
        float s = bc[c] + g_agg[o];
        g_agg[o] = 0.f;                 // restore invariant for next step/call
#pragma unroll 16
        for (int k = 0; k < 64; k++) s += hr[k] * Wr[k * 64 + c];
        mm[c] = fmaxf(s, 0.f);
    }
    __syncthreads();
    float si = bih[c], sh = bhh[c];
#pragma unroll 16
    for (int k = 0; k < 64; k++) {
        si += mm[k] * wih[k * 192 + c];
        sh += hr[k] * whh[k * 192 + c];
    }
    gi[c] = si; gh[c] = sh;
    __syncthreads();
    if (c < 64) {
        float r = 1.f / (1.f + expf(-(gi[c] + gh[c])));
        float z = 1.f / (1.f + expf(-(gi[64 + c] + gh[64 + c])));
        float nc = tanhf(gi[128 + c] + r * gh[128 + c]);
        float v = (1.f - z) * nc + z * hr[c];
        size_t o = (size_t)n * 64 + c;
        g_h[o] = v;
        __half a, b; split16(v, a, b);
        g_h1[o] = a; g_h2[o] = b;
    }
}

// ---------------- K7: edge-update MLP, 32-edge CTAs, occ 2 -----------------
// 1024 CTAs. 8 warps: mf = w&1 (16 rows), nh = w>>1 (32 cols).
// L1 (K=256): A limbs in smem (2 x 32x528); B1 plane-SEQUENTIAL (V1 then V2)
// in one 128x528 buffer. Passes: (a1V1 + a2V1) then (a1V2). Exact numerics.
// L2 (K=128): t limbs -> A region (272-stride); B2 both planes (2 x 128x272).
// smem: sc@0 tc@128 b1s@512 b2s@1024 | A@1536 (33792) | B@35328 (69632) = 104960
#define EU_SMEM   104960
#define EU_OFF_A  1536
#define EU_A_PL   16896
#define EU_OFF_B  35328
#define EU_T_PL   8704
#define EU_B2_PL  34816
extern "C" __global__ void __launch_bounds__(256, 2)
k_edgeup_tc(const int* __restrict__ eidx,
            const float* __restrict__ b1, const float* __restrict__ b2) {
    extern __shared__ char sm[];
    const uint32_t sbase = smem_u32(sm);
    int* sc = (int*)sm;
    int* tcs = (int*)(sm + 128);
    float* b1s = (float*)(sm + 512);
    float* b2s = (float*)(sm + 1024);

    const int tid = threadIdx.x;
    const int e0 = blockIdx.x * 32;
    const int w = tid >> 5, lane = tid & 31;

    if (tid < 32)      sc[tid] = eidx[e0 + tid];
    else if (tid < 64) tcs[tid - 32] = eidx[N_EDGES + e0 + (tid - 32)];
    else if (tid < 192) b1s[tid - 64] = b1[tid - 64];
    else               b2s[tid - 192] = b2[tid - 192];   // only 64; rest below
    if (tid < 64) b2s[64 + tid] = b2[64 + tid];

    // B1 plane V1: 128 rows x 32 chunks
    for (int i = tid; i < 4096; i += 256) {
        int n = i >> 5, c = i & 31;
        CP_ASYNC16(sbase + EU_OFF_B + n * 528 + c * 16,
                   g_We1T1 + (size_t)n * 256 + c * 8);
    }
    CP_COMMIT();
    __syncthreads();

    // A staging: limbs of [h_src | h_tgt | e], 32 rows x 528B, 2 planes
    for (int i = tid; i < 512; i += 256) {            // h sections
        int s = i >> 8, j = i & 255;
        int l = j >> 3, c = (j & 7) * 8;
        int nrow = s ? tcs[l] : sc[l];
        const uint4* s1 = (const uint4*)(g_h1 + (size_t)nrow * 64 + c);
        const uint4* s2 = (const uint4*)(g_h2 + (size_t)nrow * 64 + c);
        char* dst = sm + EU_OFF_A + l * 528 + s * 128 + c * 2;
        *(uint4*)dst = *s1;
        *(uint4*)(dst + EU_A_PL) = *s2;
    }
    for (int i = tid; i < 512; i += 256) {            // e section
        int l = i >> 4, c = (i & 15) * 8;
        const uint4* s1 = (const uint4*)(g_e1 + (size_t)(e0 + l) * 128 + c);
        const uint4* s2 = (const uint4*)(g_e2 + (size_t)(e0 + l) * 128 + c);
        char* dst = sm + EU_OFF_A + l * 528 + 256 + c * 2;
        *(uint4*)dst = *s1;
        *(uint4*)(dst + EU_A_PL) = *s2;
    }
    CP_WAIT_ALL();
    __syncthreads();

    const int mf = w & 1, nh = w >> 1;
    const int nbase = nh * 32;
    const int gid = lane >> 2, tpair = (lane & 3) * 2;
    const uint32_t aoff = (uint32_t)((16 * mf + (lane & 15)) * 528 + (lane >> 4) * 16);
    // nf-pair over B rows: pair p covers n8 groups 2p, 2p+1 (stride 8448)
    const uint32_t boff = (uint32_t)((nbase + (lane >> 4) * 8 + (lane & 7)) * 528 +
                                     ((lane >> 3) & 1) * 16);

    float C[4][4];
#pragma unroll
    for (int nf = 0; nf < 4; nf++) {
        float2 bv = *(const float2*)(b1s + nbase + nf * 8 + tpair);
        C[nf][0] = bv.x; C[nf][1] = bv.y;
        C[nf][2] = bv.x; C[nf][3] = bv.y;
    }

    // ---- L1 pass over V1: a1*V1 + a2*V1 ----
#pragma unroll
    for (int kf = 0; kf < 16; kf++) {
        uint32_t fa1[4], fa2[4];
        LDSM4(fa1, sbase + EU_OFF_A + aoff + kf * 32);
        LDSM4(fa2, sbase + EU_OFF_A + EU_A_PL + aoff + kf * 32);
#pragma unroll
        for (int p = 0; p < 2; p++) {
            uint32_t b[4];
            LDSM4(b, sbase + EU_OFF_B + boff + p * 8448 + kf * 32);
            MMA_F16(C[2 * p],     fa1, b[0], b[1]);
            MMA_F16(C[2 * p],     fa2, b[0], b[1]);
            MMA_F16(C[2 * p + 1], fa1, b[2], b[3]);
            MMA_F16(C[2 * p + 1], fa2, b[2], b[3]);
        }
    }
    __syncthreads();   // V1 consumed

    // stage V2 into same buffer
    for (int i = tid; i < 4096; i += 256) {
        int n = i >> 5, c = i & 31;
        CP_ASYNC16(sbase + EU_OFF_B + n * 528 + c * 16,
                   g_We1T2 + (size_t)n * 256 + c * 8);
    }
    CP_COMMIT();
    CP_WAIT_ALL();
    __syncthreads();

    // ---- L1 pass over V2: a1*V2 ----
#pragma unroll
    for (int kf = 0; kf < 16; kf++) {
        uint32_t fa1[4];
        LDSM4(fa1, sbase + EU_OFF_A + aoff + kf * 32);
#pragma unroll
        for (int p = 0; p < 2; p++) {
            uint32_t b[4];
            LDSM4(b, sbase + EU_OFF_B + boff + p * 8448 + kf * 32);
            MMA_F16(C[2 * p],     fa1, b[0], b[1]);
            MMA_F16(C[2 * p + 1], fa1, b[2], b[3]);
        }
    }
    __syncthreads();   // A reads + V2 reads done

    // stage B2 (both planes) into B region
    for (int i = tid; i < 4096; i += 256) {
        int p = i >> 11, n = (i >> 4) & 127, c = i & 15;
        const __half* src = (p ? g_We2T2 : g_We2T1) + (size_t)n * 128 + c * 8;
        CP_ASYNC16(sbase + EU_OFF_B + p * EU_B2_PL + n * 272 + c * 16, src);
    }
    CP_COMMIT();

    // t limbs -> A region (272-stride, t1 @0, t2 @ +EU_T_PL)
    {
        int r0 = 16 * mf + gid;
#pragma unroll
        for (int nf = 0; nf < 4; nf++) {
            int col = nbase + nf * 8 + tpair;
#pragma unroll
            for (int half = 0; half < 2; half++) {
                int r = r0 + half * 8;
                float v0 = fmaxf(C[nf][2 * half], 0.f);
                float v1 = fmaxf(C[nf][2 * half + 1], 0.f);
                __half a0, c0, a1_, c1;
                split16(v0, a0, c0);
                split16(v1, a1_, c1);
                char* base = sm + EU_OFF_A + r * 272 + col * 2;
                *(__half2*)base = __halves2half2(a0, a1_);
                *(__half2*)(base + EU_T_PL) = __halves2half2(c0, c1);
            }
        }
    }
    CP_WAIT_ALL();
    __syncthreads();

    // ---- Layer 2 (dual-plane lane-half LDSM: b01=limb1, b23=limb2) ----
    const uint32_t toff = (uint32_t)((16 * mf + (lane & 15)) * 272 + (lane >> 4) * 16);
    const uint32_t b2off = (uint32_t)((nbase + (lane & 7)) * 272 +
                                      ((lane >> 3) & 1) * 16 +
                                      (lane >> 4) * EU_B2_PL);
    float C2[4][4];
#pragma unroll
    for (int nf = 0; nf < 4; nf++) {
        float2 bv = *(const float2*)(b2s + nbase + nf * 8 + tpair);
        C2[nf][0] = bv.x; C2[nf][1] = bv.y;
        C2[nf][2] = bv.x; C2[nf][3] = bv.y;
    }
#pragma unroll
    for (int kf = 0; kf < 8; kf++) {
        uint32_t fa1[4], fa2[4];
        LDSM4(fa1, sbase + EU_OFF_A + toff + kf * 32);
        LDSM4(fa2, sbase + EU_OFF_A + EU_T_PL + toff + kf * 32);
#pragma unroll
        for (int nf = 0; nf < 4; nf++) {
            uint32_t b[4];
            LDSM4(b, sbase + EU_OFF_B + b2off + nf * 2176 + kf * 32);
            MMA_F16(C2[nf], fa1, b[0], b[1]);
            MMA_F16(C2[nf], fa2, b[0], b[1]);
            MMA_F16(C2[nf], fa1, b[2], b[3]);
        }
    }

    // output: e_new fp32 + fp16 limbs
    {
        int r0 = 16 * mf + gid;
#pragma unroll
        for (int nf = 0; nf < 4; nf++) {
            int col = nbase + nf * 8 + tpair;
#pragma unroll
            for (int half = 0; half < 2; half++) {
                int r = r0 + half * 8;
                size_t o = (size_t)(e0 + r) * 128 + col;
                float v0 = fmaxf(C2[nf][2 * half], 0.f);
                float v1 = fmaxf(C2[nf][2 * half + 1], 0.f);
                g_e[o] = v0; g_e[o + 1] = v1;
                __half a0, c0, a1_, c1;
                split16(v0, a0, c0);
                split16(v1, a1_, c1);
                *(__half2*)(g_e1 + o) = __halves2half2(a0, a1_);
                *(__half2*)(g_e2 + o) = __halves2half2(c0, c1);
            }
        }
    }
}

// ---------------- output copy ----------------------------------------------
__global__ void k_out(float4* __restrict__ out) {
    const int H4 = (N_NODES * DIM) / 4;
    const int T4 = H4 + (N_EDGES * EHID) / 4;
    int idx = blockIdx.x * blockDim.x + threadIdx.x;
    const float4* h4 = (const float4*)g_h;
    const float4* e4 = (const float4*)g_e;
    for (int i = idx; i < T4; i += gridDim.x * blockDim.x)
        out[i] = (i < H4) ? h4[i] : e4[i - H4];
}

// ---------------- launcher -------------------------------------------------
extern "C" void kernel_launch(void* const* d_in, const int* in_sizes, int n_in,
                              void* d_out, int out_size) {
    const float* nf   = (const float*)d_in[0];
    const float* ea   = (const float*)d_in[1];
    const int*   eidx = (const int*)  d_in[2];
    const float* Wp   = (const float*)d_in[3];
    const float* bp   = (const float*)d_in[4];
    const float* Wpe  = (const float*)d_in[5];
    const float* bpe  = (const float*)d_in[6];
    const float* Wnn  = (const float*)d_in[7];
    const float* bnn  = (const float*)d_in[8];
    const float* Wr   = (const float*)d_in[9];
    const float* bc   = (const float*)d_in[10];
    const float* wih  = (const float*)d_in[11];
    const float* whh  = (const float*)d_in[12];
    const float* bih  = (const float*)d_in[13];
    const float* bhh  = (const float*)d_in[14];
    const float* We1  = (const float*)d_in[15];
    const float* be1  = (const float*)d_in[16];
    const float* We2  = (const float*)d_in[17];
    const float* be2  = (const float*)d_in[18];

    cudaFuncSetAttribute(k_nnconv_mma, cudaFuncAttributeMaxDynamicSharedMemorySize, NC_SMEM);
    cudaFuncSetAttribute(k_edgeup_tc, cudaFuncAttributeMaxDynamicSharedMemorySize, EU_SMEM);

    k_split_t<<<dim3(128, 4), dim3(32, 8)>>>(Wnn, 128, 4096, 0);
    k_split_t<<<dim3(4, 8),   dim3(32, 8)>>>(We1, 256, 128, 1);
    k_split_t<<<dim3(4, 4),   dim3(32, 8)>>>(We2, 128, 128, 2);
    k_proj_nodes<<<N_NODES / 4, 256>>>(nf, Wp, bp);
    k_proj_edges<<<N_EDGES / 2, 256>>>(ea, Wpe, bpe);

    for (int step = 0; step < NUM_STEPS; step++) {
        k_nnconv_mma<<<(N_EDGES / 128) * 4, 256, NC_SMEM>>>(eidx, bnn);
        k_conv_gru<<<N_NODES, 192>>>(Wr, bc, wih, whh, bih, bhh);
        k_edgeup_tc<<<N_EDGES / 32, 256, EU_SMEM>>>(eidx, be1, be2);
    }

    k_out<<<2048, 256>>>((float4*)d_out);
}

// round 7
// speedup vs baseline: 5.5471x; 1.0276x over previous
#include <cuda_runtime.h>
#include <cuda_fp16.h>
#include <math.h>
#include <stdint.h>

#define N_NODES 4096
#define N_EDGES 32768
#define DIM 64
#define EHID 128
#define NUM_STEPS 3

// ---------------- scratch (device globals; zero-initialized) ----------------
__device__ float g_h[N_NODES * DIM];
__device__ float g_e[N_EDGES * EHID];
__device__ float g_agg[N_NODES * DIM];    // invariant: zero at kernel_launch entry
__device__ __half g_h1[N_NODES * DIM];
__device__ __half g_h2[N_NODES * DIM];
__device__ __half g_e1[N_EDGES * EHID];
__device__ __half g_e2[N_EDGES * EHID];
__device__ __half g_Wt1[4096 * 128];      // W_nn^T [n][k] limb1
__device__ __half g_We1T1[128 * 256];
__device__ __half g_We1T2[128 * 256];
__device__ __half g_We2T1[128 * 128];
__device__ __half g_We2T2[128 * 128];

// ---------------- helpers ---------------------------------------------------
__device__ __forceinline__ uint32_t smem_u32(const void* p) {
    uint32_t a;
    asm("{ .reg .u64 t; cvta.to.shared.u64 t, %1; cvt.u32.u64 %0, t; }"
        : "=r"(a) : "l"(p));
    return a;
}
#define LDSM4(r, addr) \
    asm volatile("ldmatrix.sync.aligned.m8n8.x4.shared.b16 {%0,%1,%2,%3}, [%4];" \
        : "=r"((r)[0]), "=r"((r)[1]), "=r"((r)[2]), "=r"((r)[3]) : "r"(addr))
#define MMA_F16(C, A, b0, b1) \
    asm volatile("mma.sync.aligned.m16n8k16.row.col.f32.f16.f16.f32 " \
        "{%0,%1,%2,%3},{%4,%5,%6,%7},{%8,%9},{%0,%1,%2,%3};" \
        : "+f"((C)[0]), "+f"((C)[1]), "+f"((C)[2]), "+f"((C)[3]) \
        : "r"((A)[0]), "r"((A)[1]), "r"((A)[2]), "r"((A)[3]), "r"(b0), "r"(b1))
#define CP_ASYNC16(dst, src) \
    asm volatile("cp.async.ca.shared.global [%0], [%1], 16;" :: "r"(dst), "l"(src))
#define CP_COMMIT() asm volatile("cp.async.commit_group;")
#define CP_WAIT_ALL() asm volatile("cp.async.wait_all;")

__device__ __forceinline__ void split16(float v, __half& a, __half& b) {
    a = __float2half(v);
    b = __float2half(v - __half2float(a));
}

// ---------------- K1: fused projections (nodes + edges) --------------------
__global__ void k_proj(const float* __restrict__ nf,
                       const float* __restrict__ Wp,
                       const float* __restrict__ bp,
                       const float* __restrict__ ea,
                       const float* __restrict__ Wpe,
                       const float* __restrict__ bpe) {
    __shared__ float s[256];
    int tid = threadIdx.x;
    if (blockIdx.x < 1024) {
        int n0 = blockIdx.x * 4;
        s[tid] = nf[(size_t)n0 * 64 + tid];
        __syncthreads();
        int nl = tid >> 6, c = tid & 63;
        float sum = bp[c];
#pragma unroll 16
        for (int k = 0; k < 64; k++) sum += s[nl * 64 + k] * Wp[k * 64 + c];
        float v = fmaxf(sum, 0.f);
        size_t o = (size_t)(n0 + nl) * 64 + c;
        g_h[o] = v;
        __half a, b; split16(v, a, b);
        g_h1[o] = a; g_h2[o] = b;
    } else {
        int e0 = (blockIdx.x - 1024) * 2;
        if (tid < 32) s[tid] = ea[(size_t)e0 * 16 + tid];
        __syncthreads();
        int el = tid >> 7, c = tid & 127;
        float sum = bpe[c];
#pragma unroll
        for (int k = 0; k < 16; k++) sum += s[el * 16 + k] * Wpe[k * 128 + c];
        float v = fmaxf(sum, 0.f);
        size_t idx = (size_t)(e0 + el) * 128 + c;
        g_e[idx] = v;
        __half a, b; split16(v, a, b);
        g_e1[idx] = a; g_e2[idx] = b;
    }
}

// ---------------- fused weight transpose + fp16 limb split -----------------
__global__ void k_split_all(const float* __restrict__ Wnn,
                            const float* __restrict__ We1,
                            const float* __restrict__ We2) {
    __shared__ float t[32][33];
    int x = threadIdx.x, y = threadIdx.y;           // 32 x 8
    int b = blockIdx.x;
    const float* W; int K, N, sel, bx, by;
    if (b < 512)      { W = Wnn; K = 128; N = 4096; sel = 0; bx = b & 127; by = b >> 7; }
    else if (b < 544) { b -= 512; W = We1; K = 256; N = 128; sel = 1; bx = b & 3; by = b >> 2; }
    else              { b -= 544; W = We2; K = 128; N = 128; sel = 2; bx = b & 3; by = b >> 2; }
    int nb = bx * 32, kb = by * 32;
#pragma unroll
    for (int i = 0; i < 4; i++)
        t[y + 8 * i][x] = W[(size_t)(kb + y + 8 * i) * N + nb + x];
    __syncthreads();
    __half* d1 = (sel == 0) ? g_Wt1 : (sel == 1) ? g_We1T1 : g_We2T1;
    __half* d2 = (sel == 1) ? g_We1T2 : g_We2T2;
#pragma unroll
    for (int i = 0; i < 4; i++) {
        float v = t[x][y + 8 * i];
        size_t o = (size_t)(nb + y + 8 * i) * K + kb + x;
        __half a, b2; split16(v, a, b2);
        d1[o] = a;
        if (sel != 0) d2[o] = b2;
    }
}

// ---------------- K4: NNConv, fp16 single-pass mma, n-split x4 -------------
// grid 1024: CTA = (128 edges) x (16-col quarter of N). 8 warps, occ 3.
// A staged in TWO 64-row rounds (region only 17408B). Per d: B = 16 rows of
// W1^T chunk d, cp.async dbl-buffered. nf-pair LDSM: 1 LDSM4 -> 2 MMA.
// smem: sc@0 tc@512 bias@1024(4096) hs@5120(33280) AB@38400(17408) = 55808
#define NC_SMEM 55808
#define OFF_BIAS 1024
#define OFF_HS   5120
#define OFF_AB   38400
extern "C" __global__ void __launch_bounds__(256, 3)
k_nnconv_mma(const int* __restrict__ eidx, const float* __restrict__ b_nn) {
    extern __shared__ char sm[];
    int* sc = (int*)sm;
    int* tcs = (int*)(sm + 512);
    float* sbias = (float*)(sm + OFF_BIAS);
    float* hs = (float*)(sm + OFF_HS);
    char* AB = sm + OFF_AB;
    const uint32_t ABu = smem_u32(AB);

    const int tid = threadIdx.x;
    const int q = blockIdx.x & 3;
    const int e0 = (blockIdx.x >> 2) * 128;
    const int ncol0 = q * 16;
    const int w = tid >> 5, lane = tid & 31;

    if (tid < 128) sc[tid] = eidx[e0 + tid];
    else           tcs[tid - 128] = eidx[N_EDGES + e0 + (tid - 128)];
    {
        int d = tid >> 2, jq = tid & 3;
        *(float4*)(sbias + d * 16 + jq * 4) =
            *(const float4*)(b_nn + d * 64 + ncol0 + jq * 4);
    }
    __syncthreads();

    // gathered h[src] -> hs (stride 65 floats)
    {
        int l = tid >> 1, d0 = (tid & 1) * 32;
        const float* hrow = g_h + (size_t)sc[l] * 64 + d0;
        float* dst = hs + l * 65 + d0;
#pragma unroll
        for (int i = 0; i < 32; i += 4) {
            float4 v = *(const float4*)(hrow + i);
            dst[i] = v.x; dst[i + 1] = v.y; dst[i + 2] = v.z; dst[i + 3] = v.w;
        }
    }

    // A fragments via two 64-row staging rounds
    uint32_t a1[8][4];
    {
        const uint4* s1 = (const uint4*)(g_e1 + (size_t)e0 * 128);
#pragma unroll
        for (int r = 0; r < 2; r++) {
            __syncthreads();
#pragma unroll
            for (int it = 0; it < 4; it++) {
                int idx = it * 256 + tid;
                int row = idx >> 4, sl = idx & 15;
                *(uint4*)(AB + row * 272 + sl * 16) = s1[(64 * r + row) * 16 + sl];
            }
            __syncthreads();
            if ((w >> 2) == r) {
                uint32_t base = ABu + (uint32_t)((16 * (w & 3) + (lane & 15)) * 272 +
                                                 (lane >> 4) * 16);
#pragma unroll
                for (int kf = 0; kf < 8; kf++) LDSM4(a1[kf], base + kf * 32);
            }
        }
        __syncthreads();   // AB becomes the B double-buffer (2 x 4352)
    }

    // B(0) -> buf 0: 16 rows x 16 chunks, one cp.async per thread
    {
        int row = tid >> 4, sl = tid & 15;
        CP_ASYNC16(ABu + row * 272 + sl * 16,
                   g_Wt1 + (size_t)(ncol0 + row) * 128 + sl * 8);
    }
    CP_COMMIT();

    const int gid = lane >> 2, tpair = (lane & 3) * 2;
    const int row0 = 16 * w + gid;
    const float* hvp0 = hs + row0 * 65;
    const float* hvp1 = hs + (row0 + 8) * 65;
    const uint32_t boff = (uint32_t)((lane & 7) * 272 + ((lane >> 3) & 1) * 16 +
                                     (lane >> 4) * 2176);
    float msg[2][4] = {};

    for (int d = 0; d < 64; d++) {
        CP_WAIT_ALL();
        __syncthreads();
        if (d + 1 < 64) {
            int row = tid >> 4, sl = tid & 15;
            CP_ASYNC16(ABu + ((d + 1) & 1) * 4352 + row * 272 + sl * 16,
                       g_Wt1 + (size_t)((d + 1) * 64 + ncol0 + row) * 128 + sl * 8);
            CP_COMMIT();
        }

        float C[2][4];
        const float* bptr = sbias + d * 16 + tpair;
#pragma unroll
        for (int nf = 0; nf < 2; nf++) {
            float2 bv = *(const float2*)(bptr + nf * 8);
            C[nf][0] = bv.x; C[nf][1] = bv.y;
            C[nf][2] = bv.x; C[nf][3] = bv.y;
        }
        const uint32_t bb = ABu + (d & 1) * 4352 + boff;
#pragma unroll
        for (int kf = 0; kf < 8; kf++) {
            uint32_t b[4];
            LDSM4(b, bb + kf * 32);
            MMA_F16(C[0], a1[kf], b[0], b[1]);
            MMA_F16(C[1], a1[kf], b[2], b[3]);
        }
        float hv0 = hvp0[d], hv1 = hvp1[d];
#pragma unroll
        for (int nf = 0; nf < 2; nf++) {
            msg[nf][0] = fmaf(hv0, fmaxf(C[nf][0], 0.f), msg[nf][0]);
            msg[nf][1] = fmaf(hv0, fmaxf(C[nf][1], 0.f), msg[nf][1]);
            msg[nf][2] = fmaf(hv1, fmaxf(C[nf][2], 0.f), msg[nf][2]);
            msg[nf][3] = fmaf(hv1, fmaxf(C[nf][3], 0.f), msg[nf][3]);
        }
    }

    float* d0 = g_agg + (size_t)tcs[row0] * 64 + ncol0 + tpair;
    float* d1 = g_agg + (size_t)tcs[row0 + 8] * 64 + ncol0 + tpair;
#pragma unroll
    for (int nf = 0; nf < 2; nf++) {
        atomicAdd(d0 + nf * 8,     msg[nf][0]);
        atomicAdd(d0 + nf * 8 + 1, msg[nf][1]);
        atomicAdd(d1 + nf * 8,     msg[nf][2]);
        atomicAdd(d1 + nf * 8 + 1, msg[nf][3]);
    }
}

// ---------------- K5+K6 fused: conv + GRU + agg re-zero (+ final out) ------
__global__ void k_conv_gru(const float* __restrict__ Wr,
                           const float* __restrict__ bc,
                           const float* __restrict__ wih,
                           const float* __restrict__ whh,
                           const float* __restrict__ bih,
                           const float* __restrict__ bhh,
                           float* __restrict__ outp) {
    __shared__ float hr[64], mm[64], gi[192], gh[192];
    int n = blockIdx.x;
    int c = threadIdx.x;   // 0..191
    if (c < 64) hr[c] = g_h[(size_t)n * 64 + c];
    __syncthreads();
    if (c < 64) {
        size_t o = (size_t)n * 64 + c;
        float s = bc[c] + g_agg[o];
        g_agg[o] = 0.f;                 // restore invariant
#pragma unroll 16
        for (int k = 0; k < 64; k++) s += hr[k] * Wr[k * 64 + c];
        mm[c] = fmaxf(s, 0.f);
    }
    __syncthreads();
    float si = bih[c], sh = bhh[c];
#pragma unroll 16
    for (int k = 0; k < 64; k++) {
        si += mm[k] * wih[k * 192 + c];
        sh += hr[k] * whh[k * 192 + c];
    }
    gi[c] = si; gh[c] = sh;
    __syncthreads();
    if (c < 64) {
        float r = 1.f / (1.f + expf(-(gi[c] + gh[c])));
        float z = 1.f / (1.f + expf(-(gi[64 + c] + gh[64 + c])));
        float nc = tanhf(gi[128 + c] + r * gh[128 + c]);
        float v = (1.f - z) * nc + z * hr[c];
        size_t o = (size_t)n * 64 + c;
        g_h[o] = v;
        if (outp) outp[o] = v;
        __half a, b; split16(v, a, b);
        g_h1[o] = a; g_h2[o] = b;
    }
}

// ---------------- K7: edge-update MLP, 32-edge CTAs, occ 2 -----------------
#define EU_SMEM   104960
#define EU_OFF_A  1536
#define EU_A_PL   16896
#define EU_OFF_B  35328
#define EU_T_PL   8704
#define EU_B2_PL  34816
extern "C" __global__ void __launch_bounds__(256, 2)
k_edgeup_tc(const int* __restrict__ eidx,
            const float* __restrict__ b1, const float* __restrict__ b2,
            float* __restrict__ oute) {
    extern __shared__ char sm[];
    const uint32_t sbase = smem_u32(sm);
    int* sc = (int*)sm;
    int* tcs = (int*)(sm + 128);
    float* b1s = (float*)(sm + 512);
    float* b2s = (float*)(sm + 1024);

    const int tid = threadIdx.x;
    const int e0 = blockIdx.x * 32;
    const int w = tid >> 5, lane = tid & 31;

    if (tid < 32)      sc[tid] = eidx[e0 + tid];
    else if (tid < 64) tcs[tid - 32] = eidx[N_EDGES + e0 + (tid - 32)];
    else if (tid < 192) b1s[tid - 64] = b1[tid - 64];
    else               b2s[tid - 192] = b2[tid - 192];
    if (tid < 64) b2s[64 + tid] = b2[64 + tid];

    // B1 plane V1: 128 rows x 32 chunks
    for (int i = tid; i < 4096; i += 256) {
        int n = i >> 5, c = i & 31;
        CP_ASYNC16(sbase + EU_OFF_B + n * 528 + c * 16,
                   g_We1T1 + (size_t)n * 256 + c * 8);
    }
    CP_COMMIT();
    __syncthreads();

    // A staging: limbs of [h_src | h_tgt | e], 32 rows x 528B, 2 planes
    for (int i = tid; i < 512; i += 256) {
        int s = i >> 8, j = i & 255;
        int l = j >> 3, c = (j & 7) * 8;
        int nrow = s ? tcs[l] : sc[l];
        const uint4* s1 = (const uint4*)(g_h1 + (size_t)nrow * 64 + c);
        const uint4* s2 = (const uint4*)(g_h2 + (size_t)nrow * 64 + c);
        char* dst = sm + EU_OFF_A + l * 528 + s * 128 + c * 2;
        *(uint4*)dst = *s1;
        *(uint4*)(dst + EU_A_PL) = *s2;
    }
    for (int i = tid; i < 512; i += 256) {
        int l = i >> 4, c = (i & 15) * 8;
        const uint4* s1 = (const uint4*)(g_e1 + (size_t)(e0 + l) * 128 + c);
        const uint4* s2 = (const uint4*)(g_e2 + (size_t)(e0 + l) * 128 + c);
        char* dst = sm + EU_OFF_A + l * 528 + 256 + c * 2;
        *(uint4*)dst = *s1;
        *(uint4*)(dst + EU_A_PL) = *s2;
    }
    CP_WAIT_ALL();
    __syncthreads();

    const int mf = w & 1, nh = w >> 1;
    const int nbase = nh * 32;
    const int gid = lane >> 2, tpair = (lane & 3) * 2;
    const uint32_t aoff = (uint32_t)((16 * mf + (lane & 15)) * 528 + (lane >> 4) * 16);
    const uint32_t boff = (uint32_t)((nbase + (lane >> 4) * 8 + (lane & 7)) * 528 +
                                     ((lane >> 3) & 1) * 16);

    float C[4][4];
#pragma unroll
    for (int nf = 0; nf < 4; nf++) {
        float2 bv = *(const float2*)(b1s + nbase + nf * 8 + tpair);
        C[nf][0] = bv.x; C[nf][1] = bv.y;
        C[nf][2] = bv.x; C[nf][3] = bv.y;
    }

    // ---- L1 pass over V1: a1*V1 + a2*V1 ----
#pragma unroll
    for (int kf = 0; kf < 16; kf++) {
        uint32_t fa1[4], fa2[4];
        LDSM4(fa1, sbase + EU_OFF_A + aoff + kf * 32);
        LDSM4(fa2, sbase + EU_OFF_A + EU_A_PL + aoff + kf * 32);
#pragma unroll
        for (int p = 0; p < 2; p++) {
            uint32_t b[4];
            LDSM4(b, sbase + EU_OFF_B + boff + p * 8448 + kf * 32);
            MMA_F16(C[2 * p],     fa1, b[0], b[1]);
            MMA_F16(C[2 * p],     fa2, b[0], b[1]);
            MMA_F16(C[2 * p + 1], fa1, b[2], b[3]);
            MMA_F16(C[2 * p + 1], fa2, b[2], b[3]);
        }
    }
    __syncthreads();

    // stage V2 into same buffer
    for (int i = tid; i < 4096; i += 256) {
        int n = i >> 5, c = i & 31;
        CP_ASYNC16(sbase + EU_OFF_B + n * 528 + c * 16,
                   g_We1T2 + (size_t)n * 256 + c * 8);
    }
    CP_COMMIT();
    CP_WAIT_ALL();
    __syncthreads();

    // ---- L1 pass over V2: a1*V2 ----
#pragma unroll
    for (int kf = 0; kf < 16; kf++) {
        uint32_t fa1[4];
        LDSM4(fa1, sbase + EU_OFF_A + aoff + kf * 32);
#pragma unroll
        for (int p = 0; p < 2; p++) {
            uint32_t b[4];
            LDSM4(b, sbase + EU_OFF_B + boff + p * 8448 + kf * 32);
            MMA_F16(C[2 * p],     fa1, b[0], b[1]);
            MMA_F16(C[2 * p + 1], fa1, b[2], b[3]);
        }
    }
    __syncthreads();

    // stage B2 (both planes)
    for (int i = tid; i < 4096; i += 256) {
        int p = i >> 11, n = (i >> 4) & 127, c = i & 15;
        const __half* src = (p ? g_We2T2 : g_We2T1) + (size_t)n * 128 + c * 8;
        CP_ASYNC16(sbase + EU_OFF_B + p * EU_B2_PL + n * 272 + c * 16, src);
    }
    CP_COMMIT();

    // t limbs -> A region
    {
        int r0 = 16 * mf + gid;
#pragma unroll
        for (int nf = 0; nf < 4; nf++) {
            int col = nbase + nf * 8 + tpair;
#pragma unroll
            for (int half = 0; half < 2; half++) {
                int r = r0 + half * 8;
                float v0 = fmaxf(C[nf][2 * half], 0.f);
                float v1 = fmaxf(C[nf][2 * half + 1], 0.f);
                __half a0, c0, a1_, c1;
                split16(v0, a0, c0);
                split16(v1, a1_, c1);
                char* base = sm + EU_OFF_A + r * 272 + col * 2;
                *(__half2*)base = __halves2half2(a0, a1_);
                *(__half2*)(base + EU_T_PL) = __halves2half2(c0, c1);
            }
        }
    }
    CP_WAIT_ALL();
    __syncthreads();

    // ---- Layer 2 ----
    const uint32_t toff = (uint32_t)((16 * mf + (lane & 15)) * 272 + (lane >> 4) * 16);
    const uint32_t b2off = (uint32_t)((nbase + (lane & 7)) * 272 +
                                      ((lane >> 3) & 1) * 16 +
                                      (lane >> 4) * EU_B2_PL);
    float C2[4][4];
#pragma unroll
    for (int nf = 0; nf < 4; nf++) {
        float2 bv = *(const float2*)(b2s + nbase + nf * 8 + tpair);
        C2[nf][0] = bv.x; C2[nf][1] = bv.y;
        C2[nf][2] = bv.x; C2[nf][3] = bv.y;
    }
#pragma unroll
    for (int kf = 0; kf < 8; kf++) {
        uint32_t fa1[4], fa2[4];
        LDSM4(fa1, sbase + EU_OFF_A + toff + kf * 32);
        LDSM4(fa2, sbase + EU_OFF_A + EU_T_PL + toff + kf * 32);
#pragma unroll
        for (int nf = 0; nf < 4; nf++) {
            uint32_t b[4];
            LDSM4(b, sbase + EU_OFF_B + b2off + nf * 2176 + kf * 32);
            MMA_F16(C2[nf], fa1, b[0], b[1]);
            MMA_F16(C2[nf], fa2, b[0], b[1]);
            MMA_F16(C2[nf], fa1, b[2], b[3]);
        }
    }

    // output: e_new fp32 + fp16 limbs (+ final d_out)
    {
        int r0 = 16 * mf + gid;
#pragma unroll
        for (int nf = 0; nf < 4; nf++) {
            int col = nbase + nf * 8 + tpair;
#pragma unroll
            for (int half = 0; half < 2; half++) {
                int r = r0 + half * 8;
                size_t o = (size_t)(e0 + r) * 128 + col;
                float v0 = fmaxf(C2[nf][2 * half], 0.f);
                float v1 = fmaxf(C2[nf][2 * half + 1], 0.f);
                g_e[o] = v0; g_e[o + 1] = v1;
                if (oute) { oute[o] = v0; oute[o + 1] = v1; }
                __half a0, c0, a1_, c1;
                split16(v0, a0, c0);
                split16(v1, a1_, c1);
                *(__half2*)(g_e1 + o) = __halves2half2(a0, a1_);
                *(__half2*)(g_e2 + o) = __halves2half2(c0, c1);
            }
        }
    }
}

// ---------------- launcher -------------------------------------------------
extern "C" void kernel_launch(void* const* d_in, const int* in_sizes, int n_in,
                              void* d_out, int out_size) {
    const float* nf   = (const float*)d_in[0];
    const float* ea   = (const float*)d_in[1];
    const int*   eidx = (const int*)  d_in[2];
    const float* Wp   = (const float*)d_in[3];
    const float* bp   = (const float*)d_in[4];
    const float* Wpe  = (const float*)d_in[5];
    const float* bpe  = (const float*)d_in[6];
    const float* Wnn  = (const float*)d_in[7];
    const float* bnn  = (const float*)d_in[8];
    const float* Wr   = (const float*)d_in[9];
    const float* bc   = (const float*)d_in[10];
    const float* wih  = (const float*)d_in[11];
    const float* whh  = (const float*)d_in[12];
    const float* bih  = (const float*)d_in[13];
    const float* bhh  = (const float*)d_in[14];
    const float* We1  = (const float*)d_in[15];
    const float* be1  = (const float*)d_in[16];
    const float* We2  = (const float*)d_in[17];
    const float* be2  = (const float*)d_in[18];

    float* out_h = (float*)d_out;
    float* out_e = (float*)d_out + (size_t)N_NODES * DIM;

    cudaFuncSetAttribute(k_nnconv_mma, cudaFuncAttributeMaxDynamicSharedMemorySize, NC_SMEM);
    cudaFuncSetAttribute(k_edgeup_tc, cudaFuncAttributeMaxDynamicSharedMemorySize, EU_SMEM);

    k_split_all<<<560, dim3(32, 8)>>>(Wnn, We1, We2);
    k_proj<<<1024 + N_EDGES / 2, 256>>>(nf, Wp, bp, ea, Wpe, bpe);

    for (int step = 0; step < NUM_STEPS; step++) {
        bool last = (step == NUM_STEPS - 1);
        k_nnconv_mma<<<(N_EDGES / 128) * 4, 256, NC_SMEM>>>(eidx, bnn);
        k_conv_gru<<<N_NODES, 192>>>(Wr, bc, wih, whh, bih, bhh,
                                     last ? out_h : (float*)nullptr);
        k_edgeup_tc<<<N_EDGES / 32, 256, EU_SMEM>>>(eidx, be1, be2,
                                                    last ? out_e : (float*)nullptr);
    }
}

// round 9
// speedup vs baseline: 5.7999x; 1.0456x over previous
#include <cuda_runtime.h>
#include <cuda_fp16.h>
#include <math.h>
#include <stdint.h>

#define N_NODES 4096
#define N_EDGES 32768
#define DIM 64
#define EHID 128
#define NUM_STEPS 3

// ---------------- scratch (device globals; zero-initialized) ----------------
__device__ float g_h[N_NODES * DIM];
__device__ float g_e[N_EDGES * EHID];
__device__ float g_agg[N_NODES * DIM];    // invariant: zero at kernel_launch entry
__device__ __half g_h1[N_NODES * DIM];
__device__ __half g_h2[N_NODES * DIM];
__device__ __half g_e1[N_EDGES * EHID];
__device__ __half g_e2[N_EDGES * EHID];
__device__ __half g_Wt1[4096 * 128];      // W_nn^T [n][k] limb1
__device__ __half g_We1T1[128 * 256];
__device__ __half g_We1T2[128 * 256];
__device__ __half g_We2T1[128 * 128];
__device__ __half g_We2T2[128 * 128];

// ---------------- helpers ---------------------------------------------------
__device__ __forceinline__ uint32_t smem_u32(const void* p) {
    uint32_t a;
    asm("{ .reg .u64 t; cvta.to.shared.u64 t, %1; cvt.u32.u64 %0, t; }"
        : "=r"(a) : "l"(p));
    return a;
}
#define LDSM4(r, addr) \
    asm volatile("ldmatrix.sync.aligned.m8n8.x4.shared.b16 {%0,%1,%2,%3}, [%4];" \
        : "=r"((r)[0]), "=r"((r)[1]), "=r"((r)[2]), "=r"((r)[3]) : "r"(addr))
#define MMA_F16(C, A, b0, b1) \
    asm volatile("mma.sync.aligned.m16n8k16.row.col.f32.f16.f16.f32 " \
        "{%0,%1,%2,%3},{%4,%5,%6,%7},{%8,%9},{%0,%1,%2,%3};" \
        : "+f"((C)[0]), "+f"((C)[1]), "+f"((C)[2]), "+f"((C)[3]) \
        : "r"((A)[0]), "r"((A)[1]), "r"((A)[2]), "r"((A)[3]), "r"(b0), "r"(b1))
#define CP_ASYNC16(dst, src) \
    asm volatile("cp.async.ca.shared.global [%0], [%1], 16;" :: "r"(dst), "l"(src))
#define CP_COMMIT() asm volatile("cp.async.commit_group;")
#define CP_WAIT_ALL() asm volatile("cp.async.wait_all;")
// NOTE: parameter names must not collide with float4 member names (.x/.y/.z/.w)
#define FMA4(accv, sclr, wvec) { (accv).x += (sclr)*(wvec).x; \
                                 (accv).y += (sclr)*(wvec).y; \
                                 (accv).z += (sclr)*(wvec).z; \
                                 (accv).w += (sclr)*(wvec).w; }

__device__ __forceinline__ void split16(float v, __half& a, __half& b) {
    a = __float2half(v);
    b = __float2half(v - __half2float(a));
}

// ---------------- K1: fused projections (nodes + edges) --------------------
__global__ void k_proj(const float* __restrict__ nf,
                       const float* __restrict__ Wp,
                       const float* __restrict__ bp,
                       const float* __restrict__ ea,
                       const float* __restrict__ Wpe,
                       const float* __restrict__ bpe) {
    __shared__ float s[256];
    int tid = threadIdx.x;
    if (blockIdx.x < 1024) {
        int n0 = blockIdx.x * 4;
        s[tid] = nf[(size_t)n0 * 64 + tid];
        __syncthreads();
        int nl = tid >> 6, c = tid & 63;
        float sum = bp[c];
#pragma unroll 16
        for (int k = 0; k < 64; k++) sum += s[nl * 64 + k] * Wp[k * 64 + c];
        float v = fmaxf(sum, 0.f);
        size_t o = (size_t)(n0 + nl) * 64 + c;
        g_h[o] = v;
        __half a, b; split16(v, a, b);
        g_h1[o] = a; g_h2[o] = b;
    } else {
        int e0 = (blockIdx.x - 1024) * 2;
        if (tid < 32) s[tid] = ea[(size_t)e0 * 16 + tid];
        __syncthreads();
        int el = tid >> 7, c = tid & 127;
        float sum = bpe[c];
#pragma unroll
        for (int k = 0; k < 16; k++) sum += s[el * 16 + k] * Wpe[k * 128 + c];
        float v = fmaxf(sum, 0.f);
        size_t idx = (size_t)(e0 + el) * 128 + c;
        g_e[idx] = v;
        __half a, b; split16(v, a, b);
        g_e1[idx] = a; g_e2[idx] = b;
    }
}

// ---------------- fused weight transpose + fp16 limb split -----------------
__global__ void k_split_all(const float* __restrict__ Wnn,
                            const float* __restrict__ We1,
                            const float* __restrict__ We2) {
    __shared__ float t[32][33];
    int x = threadIdx.x, y = threadIdx.y;           // 32 x 8
    int b = blockIdx.x;
    const float* W; int K, N, sel, bx, by;
    if (b < 512)      { W = Wnn; K = 128; N = 4096; sel = 0; bx = b & 127; by = b >> 7; }
    else if (b < 544) { b -= 512; W = We1; K = 256; N = 128; sel = 1; bx = b & 3; by = b >> 2; }
    else              { b -= 544; W = We2; K = 128; N = 128; sel = 2; bx = b & 3; by = b >> 2; }
    int nb = bx * 32, kb = by * 32;
#pragma unroll
    for (int i = 0; i < 4; i++)
        t[y + 8 * i][x] = W[(size_t)(kb + y + 8 * i) * N + nb + x];
    __syncthreads();
    __half* d1 = (sel == 0) ? g_Wt1 : (sel == 1) ? g_We1T1 : g_We2T1;
    __half* d2 = (sel == 1) ? g_We1T2 : g_We2T2;
#pragma unroll
    for (int i = 0; i < 4; i++) {
        float v = t[x][y + 8 * i];
        size_t o = (size_t)(nb + y + 8 * i) * K + kb + x;
        __half a, b2; split16(v, a, b2);
        d1[o] = a;
        if (sel != 0) d2[o] = b2;
    }
}

// ---------------- K4: NNConv, fp16 single-pass mma, n-split x4 -------------
#define NC_SMEM 55808
#define OFF_BIAS 1024
#define OFF_HS   5120
#define OFF_AB   38400
extern "C" __global__ void __launch_bounds__(256, 3)
k_nnconv_mma(const int* __restrict__ eidx, const float* __restrict__ b_nn) {
    extern __shared__ char sm[];
    int* sc = (int*)sm;
    int* tcs = (int*)(sm + 512);
    float* sbias = (float*)(sm + OFF_BIAS);
    float* hs = (float*)(sm + OFF_HS);
    char* AB = sm + OFF_AB;
    const uint32_t ABu = smem_u32(AB);

    const int tid = threadIdx.x;
    const int q = blockIdx.x & 3;
    const int e0 = (blockIdx.x >> 2) * 128;
    const int ncol0 = q * 16;
    const int w = tid >> 5, lane = tid & 31;

    if (tid < 128) sc[tid] = eidx[e0 + tid];
    else           tcs[tid - 128] = eidx[N_EDGES + e0 + (tid - 128)];
    {
        int d = tid >> 2, jq = tid & 3;
        *(float4*)(sbias + d * 16 + jq * 4) =
            *(const float4*)(b_nn + d * 64 + ncol0 + jq * 4);
    }
    __syncthreads();

    {
        int l = tid >> 1, d0 = (tid & 1) * 32;
        const float* hrow = g_h + (size_t)sc[l] * 64 + d0;
        float* dst = hs + l * 65 + d0;
#pragma unroll
        for (int i = 0; i < 32; i += 4) {
            float4 v = *(const float4*)(hrow + i);
            dst[i] = v.x; dst[i + 1] = v.y; dst[i + 2] = v.z; dst[i + 3] = v.w;
        }
    }

    uint32_t a1[8][4];
    {
        const uint4* s1 = (const uint4*)(g_e1 + (size_t)e0 * 128);
#pragma unroll
        for (int r = 0; r < 2; r++) {
            __syncthreads();
#pragma unroll
            for (int it = 0; it < 4; it++) {
                int idx = it * 256 + tid;
                int row = idx >> 4, sl = idx & 15;
                *(uint4*)(AB + row * 272 + sl * 16) = s1[(64 * r + row) * 16 + sl];
            }
            __syncthreads();
            if ((w >> 2) == r) {
                uint32_t base = ABu + (uint32_t)((16 * (w & 3) + (lane & 15)) * 272 +
                                                 (lane >> 4) * 16);
#pragma unroll
                for (int kf = 0; kf < 8; kf++) LDSM4(a1[kf], base + kf * 32);
            }
        }
        __syncthreads();
    }

    {
        int row = tid >> 4, sl = tid & 15;
        CP_ASYNC16(ABu + row * 272 + sl * 16,
                   g_Wt1 + (size_t)(ncol0 + row) * 128 + sl * 8);
    }
    CP_COMMIT();

    const int gid = lane >> 2, tpair = (lane & 3) * 2;
    const int row0 = 16 * w + gid;
    const float* hvp0 = hs + row0 * 65;
    const float* hvp1 = hs + (row0 + 8) * 65;
    const uint32_t boff = (uint32_t)((lane & 7) * 272 + ((lane >> 3) & 1) * 16 +
                                     (lane >> 4) * 2176);
    float msg[2][4] = {};

    for (int d = 0; d < 64; d++) {
        CP_WAIT_ALL();
        __syncthreads();
        if (d + 1 < 64) {
            int row = tid >> 4, sl = tid & 15;
            CP_ASYNC16(ABu + ((d + 1) & 1) * 4352 + row * 272 + sl * 16,
                       g_Wt1 + (size_t)((d + 1) * 64 + ncol0 + row) * 128 + sl * 8);
            CP_COMMIT();
        }

        float C[2][4];
        const float* bptr = sbias + d * 16 + tpair;
#pragma unroll
        for (int nf = 0; nf < 2; nf++) {
            float2 bv = *(const float2*)(bptr + nf * 8);
            C[nf][0] = bv.x; C[nf][1] = bv.y;
            C[nf][2] = bv.x; C[nf][3] = bv.y;
        }
        const uint32_t bb = ABu + (d & 1) * 4352 + boff;
#pragma unroll
        for (int kf = 0; kf < 8; kf++) {
            uint32_t b[4];
            LDSM4(b, bb + kf * 32);
            MMA_F16(C[0], a1[kf], b[0], b[1]);
            MMA_F16(C[1], a1[kf], b[2], b[3]);
        }
        float hv0 = hvp0[d], hv1 = hvp1[d];
#pragma unroll
        for (int nf = 0; nf < 2; nf++) {
            msg[nf][0] = fmaf(hv0, fmaxf(C[nf][0], 0.f), msg[nf][0]);
            msg[nf][1] = fmaf(hv0, fmaxf(C[nf][1], 0.f), msg[nf][1]);
            msg[nf][2] = fmaf(hv1, fmaxf(C[nf][2], 0.f), msg[nf][2]);
            msg[nf][3] = fmaf(hv1, fmaxf(C[nf][3], 0.f), msg[nf][3]);
        }
    }

    float* d0 = g_agg + (size_t)tcs[row0] * 64 + ncol0 + tpair;
    float* d1 = g_agg + (size_t)tcs[row0 + 8] * 64 + ncol0 + tpair;
#pragma unroll
    for (int nf = 0; nf < 2; nf++) {
        atomicAdd(d0 + nf * 8,     msg[nf][0]);
        atomicAdd(d0 + nf * 8 + 1, msg[nf][1]);
        atomicAdd(d1 + nf * 8,     msg[nf][2]);
        atomicAdd(d1 + nf * 8 + 1, msg[nf][3]);
    }
}

// ---------------- K5+K6: conv + GRU, smem-cached weights, 32 nodes/CTA -----
// grid 128. smem (floats): Wr@0(4096) Wih@4096(12288) Whh@16384(12288)
// hr@28672(2176,stride 68) mm@30848(2176) gi@33024(6272,stride 196) gh@39296
// total 45568 floats = 182272 B. Bitwise-identical math to the old kernel.
#define CG_SMEM 182272
__global__ void __launch_bounds__(256, 1)
k_conv_gru(const float* __restrict__ Wr,  const float* __restrict__ bc,
           const float* __restrict__ wih, const float* __restrict__ whh,
           const float* __restrict__ bih, const float* __restrict__ bhh,
           float* __restrict__ outp) {
    extern __shared__ float s[];
    float* sWr  = s;
    float* sWih = s + 4096;
    float* sWhh = s + 16384;
    float* shr  = s + 28672;
    float* smm  = s + 30848;
    float* sgi  = s + 33024;
    float* sgh  = s + 39296;

    const int tid = threadIdx.x;
    const int n0 = blockIdx.x * 32;

    // weights -> smem
    for (int i = tid; i < 1024; i += 256)
        ((float4*)sWr)[i] = ((const float4*)Wr)[i];
    for (int i = tid; i < 3072; i += 256) {
        ((float4*)sWih)[i] = ((const float4*)wih)[i];
        ((float4*)sWhh)[i] = ((const float4*)whh)[i];
    }
    // h rows -> shr (stride 68)
    for (int i = tid; i < 512; i += 256) {
        int n = i >> 4, c4 = (i & 15) * 4;
        *(float4*)(shr + n * 68 + c4) =
            *(const float4*)(g_h + (size_t)(n0 + n) * 64 + c4);
    }
    __syncthreads();

    // ---- phase A: m = relu(agg + h@Wr + bc), 2 nodes x 16 col4 per thread
    {
        int pr = tid >> 4;                  // 0..15 -> nodes 2pr, 2pr+1
        int c4 = (tid & 15) * 4;
        int na = pr * 2, nbd = na + 1;
        float4 bc4 = *(const float4*)(bc + c4);
        float* aggp0 = g_agg + (size_t)(n0 + na) * 64 + c4;
        float* aggp1 = g_agg + (size_t)(n0 + nbd) * 64 + c4;
        float4 acc0 = *(const float4*)aggp0;
        float4 acc1 = *(const float4*)aggp1;
        *(float4*)aggp0 = make_float4(0.f, 0.f, 0.f, 0.f);
        *(float4*)aggp1 = make_float4(0.f, 0.f, 0.f, 0.f);
        acc0.x += bc4.x; acc0.y += bc4.y; acc0.z += bc4.z; acc0.w += bc4.w;
        acc1.x += bc4.x; acc1.y += bc4.y; acc1.z += bc4.z; acc1.w += bc4.w;
        for (int k4 = 0; k4 < 64; k4 += 4) {
            float4 wv0 = *(const float4*)(sWr + (k4 + 0) * 64 + c4);
            float4 wv1 = *(const float4*)(sWr + (k4 + 1) * 64 + c4);
            float4 wv2 = *(const float4*)(sWr + (k4 + 2) * 64 + c4);
            float4 wv3 = *(const float4*)(sWr + (k4 + 3) * 64 + c4);
            float4 ha = *(const float4*)(shr + na * 68 + k4);
            float4 hb = *(const float4*)(shr + nbd * 68 + k4);
            FMA4(acc0, ha.x, wv0); FMA4(acc0, ha.y, wv1);
            FMA4(acc0, ha.z, wv2); FMA4(acc0, ha.w, wv3);
            FMA4(acc1, hb.x, wv0); FMA4(acc1, hb.y, wv1);
            FMA4(acc1, hb.z, wv2); FMA4(acc1, hb.w, wv3);
        }
        acc0.x = fmaxf(acc0.x, 0.f); acc0.y = fmaxf(acc0.y, 0.f);
        acc0.z = fmaxf(acc0.z, 0.f); acc0.w = fmaxf(acc0.w, 0.f);
        acc1.x = fmaxf(acc1.x, 0.f); acc1.y = fmaxf(acc1.y, 0.f);
        acc1.z = fmaxf(acc1.z, 0.f); acc1.w = fmaxf(acc1.w, 0.f);
        *(float4*)(smm + na * 68 + c4) = acc0;
        *(float4*)(smm + nbd * 68 + c4) = acc1;
    }
    __syncthreads();

    // ---- phase B: gi = m@wih + bih, gh = h@whh + bhh; 4 nodes x 4 cols/task
    for (int task = tid; task < 384; task += 256) {
        int ng = task / 48;
        int c4 = (task - ng * 48) * 4;
        int nb0 = ng * 4;
        float4 bi4 = *(const float4*)(bih + c4);
        float4 bh4 = *(const float4*)(bhh + c4);
        float4 agi[4], agh[4];
#pragma unroll
        for (int nn = 0; nn < 4; nn++) { agi[nn] = bi4; agh[nn] = bh4; }
        for (int k4 = 0; k4 < 64; k4 += 4) {
            float4 wi0 = *(const float4*)(sWih + (k4 + 0) * 192 + c4);
            float4 wi1 = *(const float4*)(sWih + (k4 + 1) * 192 + c4);
            float4 wi2 = *(const float4*)(sWih + (k4 + 2) * 192 + c4);
            float4 wi3 = *(const float4*)(sWih + (k4 + 3) * 192 + c4);
            float4 wh0 = *(const float4*)(sWhh + (k4 + 0) * 192 + c4);
            float4 wh1 = *(const float4*)(sWhh + (k4 + 1) * 192 + c4);
            float4 wh2 = *(const float4*)(sWhh + (k4 + 2) * 192 + c4);
            float4 wh3 = *(const float4*)(sWhh + (k4 + 3) * 192 + c4);
#pragma unroll
            for (int nn = 0; nn < 4; nn++) {
                float4 m4 = *(const float4*)(smm + (nb0 + nn) * 68 + k4);
                float4 h4 = *(const float4*)(shr + (nb0 + nn) * 68 + k4);
                FMA4(agi[nn], m4.x, wi0); FMA4(agi[nn], m4.y, wi1);
                FMA4(agi[nn], m4.z, wi2); FMA4(agi[nn], m4.w, wi3);
                FMA4(agh[nn], h4.x, wh0); FMA4(agh[nn], h4.y, wh1);
                FMA4(agh[nn], h4.z, wh2); FMA4(agh[nn], h4.w, wh3);
            }
        }
#pragma unroll
        for (int nn = 0; nn < 4; nn++) {
            *(float4*)(sgi + (nb0 + nn) * 196 + c4) = agi[nn];
            *(float4*)(sgh + (nb0 + nn) * 196 + c4) = agh[nn];
        }
    }
    __syncthreads();

    // ---- gates ----
    for (int i = tid; i < 2048; i += 256) {
        int n = i >> 6, c = i & 63;
        const float* gi = sgi + n * 196;
        const float* gh = sgh + n * 196;
        float r = 1.f / (1.f + expf(-(gi[c] + gh[c])));
        float z = 1.f / (1.f + expf(-(gi[64 + c] + gh[64 + c])));
        float nc = tanhf(gi[128 + c] + r * gh[128 + c]);
        float v = (1.f - z) * nc + z * shr[n * 68 + c];
        size_t o = (size_t)(n0 + n) * 64 + c;
        g_h[o] = v;
        if (outp) outp[o] = v;
        __half a, b; split16(v, a, b);
        g_h1[o] = a; g_h2[o] = b;
    }
}

// ---------------- K7: edge-update MLP, 32-edge CTAs, occ 2 -----------------
#define EU_SMEM   104960
#define EU_OFF_A  1536
#define EU_A_PL   16896
#define EU_OFF_B  35328
#define EU_T_PL   8704
#define EU_B2_PL  34816
extern "C" __global__ void __launch_bounds__(256, 2)
k_edgeup_tc(const int* __restrict__ eidx,
            const float* __restrict__ b1, const float* __restrict__ b2,
            float* __restrict__ oute) {
    extern __shared__ char sm[];
    const uint32_t sbase = smem_u32(sm);
    int* sc = (int*)sm;
    int* tcs = (int*)(sm + 128);
    float* b1s = (float*)(sm + 512);
    float* b2s = (float*)(sm + 1024);

    const int tid = threadIdx.x;
    const int e0 = blockIdx.x * 32;
    const int w = tid >> 5, lane = tid & 31;

    if (tid < 32)      sc[tid] = eidx[e0 + tid];
    else if (tid < 64) tcs[tid - 32] = eidx[N_EDGES + e0 + (tid - 32)];
    else if (tid < 192) b1s[tid - 64] = b1[tid - 64];
    else               b2s[tid - 192] = b2[tid - 192];
    if (tid < 64) b2s[64 + tid] = b2[64 + tid];

    for (int i = tid; i < 4096; i += 256) {
        int n = i >> 5, c = i & 31;
        CP_ASYNC16(sbase + EU_OFF_B + n * 528 + c * 16,
                   g_We1T1 + (size_t)n * 256 + c * 8);
    }
    CP_COMMIT();
    __syncthreads();

    for (int i = tid; i < 512; i += 256) {
        int s2 = i >> 8, j = i & 255;
        int l = j >> 3, c = (j & 7) * 8;
        int nrow = s2 ? tcs[l] : sc[l];
        const uint4* s1 = (const uint4*)(g_h1 + (size_t)nrow * 64 + c);
        const uint4* s2p = (const uint4*)(g_h2 + (size_t)nrow * 64 + c);
        char* dst = sm + EU_OFF_A + l * 528 + s2 * 128 + c * 2;
        *(uint4*)dst = *s1;
        *(uint4*)(dst + EU_A_PL) = *s2p;
    }
    for (int i = tid; i < 512; i += 256) {
        int l = i >> 4, c = (i & 15) * 8;
        const uint4* s1 = (const uint4*)(g_e1 + (size_t)(e0 + l) * 128 + c);
        const uint4* s2p = (const uint4*)(g_e2 + (size_t)(e0 + l) * 128 + c);
        char* dst = sm + EU_OFF_A + l * 528 + 256 + c * 2;
        *(uint4*)dst = *s1;
        *(uint4*)(dst + EU_A_PL) = *s2p;
    }
    CP_WAIT_ALL();
    __syncthreads();

    const int mf = w & 1, nh = w >> 1;
    const int nbase = nh * 32;
    const int gid = lane >> 2, tpair = (lane & 3) * 2;
    const uint32_t aoff = (uint32_t)((16 * mf + (lane & 15)) * 528 + (lane >> 4) * 16);
    const uint32_t boff = (uint32_t)((nbase + (lane >> 4) * 8 + (lane & 7)) * 528 +
                                     ((lane >> 3) & 1) * 16);

    float C[4][4];
#pragma unroll
    for (int nf = 0; nf < 4; nf++) {
        float2 bv = *(const float2*)(b1s + nbase + nf * 8 + tpair);
        C[nf][0] = bv.x; C[nf][1] = bv.y;
        C[nf][2] = bv.x; C[nf][3] = bv.y;
    }

#pragma unroll
    for (int kf = 0; kf < 16; kf++) {
        uint32_t fa1[4], fa2[4];
        LDSM4(fa1, sbase + EU_OFF_A + aoff + kf * 32);
        LDSM4(fa2, sbase + EU_OFF_A + EU_A_PL + aoff + kf * 32);
#pragma unroll
        for (int p = 0; p < 2; p++) {
            uint32_t b[4];
            LDSM4(b, sbase + EU_OFF_B + boff + p * 8448 + kf * 32);
            MMA_F16(C[2 * p],     fa1, b[0], b[1]);
            MMA_F16(C[2 * p],     fa2, b[0], b[1]);
            MMA_F16(C[2 * p + 1], fa1, b[2], b[3]);
            MMA_F16(C[2 * p + 1], fa2, b[2], b[3]);
        }
    }
    __syncthreads();

    for (int i = tid; i < 4096; i += 256) {
        int n = i >> 5, c = i & 31;
        CP_ASYNC16(sbase + EU_OFF_B + n * 528 + c * 16,
                   g_We1T2 + (size_t)n * 256 + c * 8);
    }
    CP_COMMIT();
    CP_WAIT_ALL();
    __syncthreads();

#pragma unroll
    for (int kf = 0; kf < 16; kf++) {
        uint32_t fa1[4];
        LDSM4(fa1, sbase + EU_OFF_A + aoff + kf * 32);
#pragma unroll
        for (int p = 0; p < 2; p++) {
            uint32_t b[4];
            LDSM4(b, sbase + EU_OFF_B + boff + p * 8448 + kf * 32);
            MMA_F16(C[2 * p],     fa1, b[0], b[1]);
            MMA_F16(C[2 * p + 1], fa1, b[2], b[3]);
        }
    }
    __syncthreads();

    for (int i = tid; i < 4096; i += 256) {
        int p = i >> 11, n = (i >> 4) & 127, c = i & 15;
        const __half* src = (p ? g_We2T2 : g_We2T1) + (size_t)n * 128 + c * 8;
        CP_ASYNC16(sbase + EU_OFF_B + p * EU_B2_PL + n * 272 + c * 16, src);
    }
    CP_COMMIT();

    {
        int r0 = 16 * mf + gid;
#pragma unroll
        for (int nf = 0; nf < 4; nf++) {
            int col = nbase + nf * 8 + tpair;
#pragma unroll
            for (int half = 0; half < 2; half++) {
                int r = r0 + half * 8;
                float v0 = fmaxf(C[nf][2 * half], 0.f);
                float v1 = fmaxf(C[nf][2 * half + 1], 0.f);
                __half a0, c0, a1_, c1;
                split16(v0, a0, c0);
                split16(v1, a1_, c1);
                char* base = sm + EU_OFF_A + r * 272 + col * 2;
                *(__half2*)base = __halves2half2(a0, a1_);
                *(__half2*)(base + EU_T_PL) = __halves2half2(c0, c1);
            }
        }
    }
    CP_WAIT_ALL();
    __syncthreads();

    const uint32_t toff = (uint32_t)((16 * mf + (lane & 15)) * 272 + (lane >> 4) * 16);
    const uint32_t b2off = (uint32_t)((nbase + (lane & 7)) * 272 +
                                      ((lane >> 3) & 1) * 16 +
                                      (lane >> 4) * EU_B2_PL);
    float C2[4][4];
#pragma unroll
    for (int nf = 0; nf < 4; nf++) {
        float2 bv = *(const float2*)(b2s + nbase + nf * 8 + tpair);
        C2[nf][0] = bv.x; C2[nf][1] = bv.y;
        C2[nf][2] = bv.x; C2[nf][3] = bv.y;
    }
#pragma unroll
    for (int kf = 0; kf < 8; kf++) {
        uint32_t fa1[4], fa2[4];
        LDSM4(fa1, sbase + EU_OFF_A + toff + kf * 32);
        LDSM4(fa2, sbase + EU_OFF_A + EU_T_PL + toff + kf * 32);
#pragma unroll
        for (int nf = 0; nf < 4; nf++) {
            uint32_t b[4];
            LDSM4(b, sbase + EU_OFF_B + b2off + nf * 2176 + kf * 32);
            MMA_F16(C2[nf], fa1, b[0], b[1]);
            MMA_F16(C2[nf], fa2, b[0], b[1]);
            MMA_F16(C2[nf], fa1, b[2], b[3]);
        }
    }

    {
        int r0 = 16 * mf + gid;
#pragma unroll
        for (int nf = 0; nf < 4; nf++) {
            int col = nbase + nf * 8 + tpair;
#pragma unroll
            for (int half = 0; half < 2; half++) {
                int r = r0 + half * 8;
                size_t o = (size_t)(e0 + r) * 128 + col;
                float v0 = fmaxf(C2[nf][2 * half], 0.f);
                float v1 = fmaxf(C2[nf][2 * half + 1], 0.f);
                g_e[o] = v0; g_e[o + 1] = v1;
                if (oute) { oute[o] = v0; oute[o + 1] = v1; }
                __half a0, c0, a1_, c1;
                split16(v0, a0, c0);
                split16(v1, a1_, c1);
                *(__half2*)(g_e1 + o) = __halves2half2(a0, a1_);
                *(__half2*)(g_e2 + o) = __halves2half2(c0, c1);
            }
        }
    }
}

// ---------------- launcher -------------------------------------------------
extern "C" void kernel_launch(void* const* d_in, const int* in_sizes, int n_in,
                              void* d_out, int out_size) {
    const float* nf   = (const float*)d_in[0];
    const float* ea   = (const float*)d_in[1];
    const int*   eidx = (const int*)  d_in[2];
    const float* Wp   = (const float*)d_in[3];
    const float* bp   = (const float*)d_in[4];
    const float* Wpe  = (const float*)d_in[5];
    const float* bpe  = (const float*)d_in[6];
    const float* Wnn  = (const float*)d_in[7];
    const float* bnn  = (const float*)d_in[8];
    const float* Wr   = (const float*)d_in[9];
    const float* bc   = (const float*)d_in[10];
    const float* wih  = (const float*)d_in[11];
    const float* whh  = (const float*)d_in[12];
    const float* bih  = (const float*)d_in[13];
    const float* bhh  = (const float*)d_in[14];
    const float* We1  = (const float*)d_in[15];
    const float* be1  = (const float*)d_in[16];
    const float* We2  = (const float*)d_in[17];
    const float* be2  = (const float*)d_in[18];

    float* out_h = (float*)d_out;
    float* out_e = (float*)d_out + (size_t)N_NODES * DIM;

    cudaFuncSetAttribute(k_nnconv_mma, cudaFuncAttributeMaxDynamicSharedMemorySize, NC_SMEM);
    cudaFuncSetAttribute(k_edgeup_tc, cudaFuncAttributeMaxDynamicSharedMemorySize, EU_SMEM);
    cudaFuncSetAttribute(k_conv_gru, cudaFuncAttributeMaxDynamicSharedMemorySize, CG_SMEM);

    k_split_all<<<560, dim3(32, 8)>>>(Wnn, We1, We2);
    k_proj<<<1024 + N_EDGES / 2, 256>>>(nf, Wp, bp, ea, Wpe, bpe);

    for (int step = 0; step < NUM_STEPS; step++) {
        bool last = (step == NUM_STEPS - 1);
        k_nnconv_mma<<<(N_EDGES / 128) * 4, 256, NC_SMEM>>>(eidx, bnn);
        k_conv_gru<<<N_NODES / 32, 256, CG_SMEM>>>(Wr, bc, wih, whh, bih, bhh,
                                                   last ? out_h : (float*)nullptr);
        k_edgeup_tc<<<N_EDGES / 32, 256, EU_SMEM>>>(eidx, be1, be2,
                                                    last ? out_e : (float*)nullptr);
    }
}